// round 1
// baseline (speedup 1.0000x reference)
#include <cuda_runtime.h>
#include <cuda_bf16.h>
#include <math.h>

// Problem constants (fixed by the reference)
#define NN 50000
#define EE 800000
#define BB 256
#define DD 128
#define HH 256
#define LL 3
#define TEMP 0.2f
#define BN_EPS 1e-5f

// ---------------- scratch (device globals; no allocation allowed) ----------------
__device__ __align__(16) float g_x[(size_t)NN * DD];
__device__ __align__(16) float g_h[(size_t)NN * DD];
__device__ __align__(16) float g_agg[(size_t)NN * DD];
__device__ __align__(16) float g_z1[(size_t)NN * HH];
__device__ __align__(16) float g_z2[(size_t)NN * DD];
__device__ __align__(16) float g_pool[2 * BB * LL * DD];   // slot0: masked/enc (gh), slot1: contrast/con (ch)
__device__ __align__(16) float g_stats[2 * HH];
__device__ __align__(16) float g_ab[2 * HH];
__device__ __align__(16) float g_p2[2 * BB * 128];         // projected embeddings
__device__ float g_norms[2 * BB];

// ---------------- kernels ----------------

__global__ void mask_kernel(float* __restrict__ x, const int* __restrict__ idx,
                            const float* __restrict__ tok, int nMask) {
    int i = blockIdx.x * blockDim.x + threadIdx.x;
    if (i >= nMask * DD) return;
    int m = i >> 7, c = i & 127;
    x[(size_t)idx[m] * DD + c] = tok[c];
}

// agg[dst] += h[src]; warp per edge, float4 per lane
__global__ void edge_agg(const float* __restrict__ hin, const int* __restrict__ src,
                         const int* __restrict__ dst, float* __restrict__ agg) {
    int idx = blockIdx.x * blockDim.x + threadIdx.x;
    int e = idx >> 5;
    if (e >= EE) return;
    int lane = idx & 31;
    int s = src[e], d = dst[e];
    float4 v = *reinterpret_cast<const float4*>(hin + (size_t)s * DD + lane * 4);
    float* p = agg + (size_t)d * DD + lane * 4;
    atomicAdd(p + 0, v.x);
    atomicAdd(p + 1, v.y);
    atomicAdd(p + 2, v.z);
    atomicAdd(p + 3, v.w);
}

// C[M,Ncols] = f(A)[M,K] @ B[K,Ncols]
// MODE 0: f(A) = A0 + A1 (GIN input)
// MODE 1: f(A) = relu(A0 * a[k] + c[k])  (BN+ReLU fused into A read)
#define BM 64
#define BN 64
#define BK 16
template <int MODE>
__global__ void sgemm(const float* __restrict__ A0, const float* __restrict__ A1,
                      const float* __restrict__ Bm, float* __restrict__ C,
                      const float* __restrict__ ab, int M, int K, int Ncols) {
    __shared__ __align__(16) float As[BK][BM];
    __shared__ __align__(16) float Bs[BK][BN];
    int bm = blockIdx.x * BM;
    int bn = blockIdx.y * BN;
    int t = threadIdx.x;              // 0..255
    int tx = t & 15, ty = t >> 4;
    float acc[4][4] = {};

    int ar = t >> 2;                  // 0..63 (row within tile)
    int akq = (t & 3) * 4;            // k quad offset
    int bkr = t >> 4;                 // 0..15
    int bnq = (t & 15) * 4;           // n quad offset

    for (int k0 = 0; k0 < K; k0 += BK) {
        int row = bm + ar;
        float4 va;
        if (row < M) {
            va = *reinterpret_cast<const float4*>(A0 + (size_t)row * K + k0 + akq);
            if (MODE == 0) {
                float4 vb = *reinterpret_cast<const float4*>(A1 + (size_t)row * K + k0 + akq);
                va.x += vb.x; va.y += vb.y; va.z += vb.z; va.w += vb.w;
            } else {
                int kk = k0 + akq;
                float4 sa = *reinterpret_cast<const float4*>(ab + kk);
                float4 sc = *reinterpret_cast<const float4*>(ab + K + kk);
                va.x = fmaxf(fmaf(va.x, sa.x, sc.x), 0.f);
                va.y = fmaxf(fmaf(va.y, sa.y, sc.y), 0.f);
                va.z = fmaxf(fmaf(va.z, sa.z, sc.z), 0.f);
                va.w = fmaxf(fmaf(va.w, sa.w, sc.w), 0.f);
            }
        } else {
            va = make_float4(0.f, 0.f, 0.f, 0.f);
        }
        As[akq + 0][ar] = va.x;
        As[akq + 1][ar] = va.y;
        As[akq + 2][ar] = va.z;
        As[akq + 3][ar] = va.w;

        float4 vb = *reinterpret_cast<const float4*>(Bm + (size_t)(k0 + bkr) * Ncols + bn + bnq);
        Bs[bkr][bnq + 0] = vb.x;
        Bs[bkr][bnq + 1] = vb.y;
        Bs[bkr][bnq + 2] = vb.z;
        Bs[bkr][bnq + 3] = vb.w;
        __syncthreads();

#pragma unroll
        for (int k = 0; k < BK; k++) {
            float4 ra = *reinterpret_cast<const float4*>(&As[k][ty * 4]);
            float4 rb = *reinterpret_cast<const float4*>(&Bs[k][tx * 4]);
            acc[0][0] += ra.x * rb.x; acc[0][1] += ra.x * rb.y; acc[0][2] += ra.x * rb.z; acc[0][3] += ra.x * rb.w;
            acc[1][0] += ra.y * rb.x; acc[1][1] += ra.y * rb.y; acc[1][2] += ra.y * rb.z; acc[1][3] += ra.y * rb.w;
            acc[2][0] += ra.z * rb.x; acc[2][1] += ra.z * rb.y; acc[2][2] += ra.z * rb.z; acc[2][3] += ra.z * rb.w;
            acc[3][0] += ra.w * rb.x; acc[3][1] += ra.w * rb.y; acc[3][2] += ra.w * rb.z; acc[3][3] += ra.w * rb.w;
        }
        __syncthreads();
    }

#pragma unroll
    for (int i = 0; i < 4; i++) {
        int row = bm + ty * 4 + i;
        if (row < M) {
            float4 o = make_float4(acc[i][0], acc[i][1], acc[i][2], acc[i][3]);
            *reinterpret_cast<float4*>(C + (size_t)row * Ncols + bn + tx * 4) = o;
        }
    }
}

// column sums / sums-of-squares; C threads per block, blocks stripe rows
__global__ void colstats(const float* __restrict__ Z, int M, int C, float* __restrict__ stats) {
    int t = threadIdx.x;
    int rowsPer = (M + gridDim.x - 1) / gridDim.x;
    int r0 = blockIdx.x * rowsPer;
    int r1 = min(M, r0 + rowsPer);
    float s = 0.f, q = 0.f;
    for (int r = r0; r < r1; r++) {
        float v = Z[(size_t)r * C + t];
        s += v;
        q += v * v;
    }
    atomicAdd(&stats[t], s);
    atomicAdd(&stats[C + t], q);
}

__global__ void ab_kernel(const float* __restrict__ stats, const float* __restrict__ g,
                          const float* __restrict__ b, int C, float invM, float* __restrict__ ab) {
    int t = threadIdx.x;
    if (t < C) {
        float m = stats[t] * invM;
        float var = stats[C + t] * invM - m * m;
        float a = g[t] * rsqrtf(var + BN_EPS);
        ab[t] = a;
        ab[C + t] = b[t] - m * a;
    }
}

// h = relu(bn(z2)); pool[gid[r], colOff + c] += h
__global__ void bnrelu_pool(const float* __restrict__ Z, const float* __restrict__ ab,
                            const int* __restrict__ gid, float* __restrict__ h,
                            float* __restrict__ pool, int colOff) {
    size_t i = (size_t)blockIdx.x * blockDim.x + threadIdx.x;
    if (i >= (size_t)NN * DD) return;
    int r = (int)(i >> 7);
    int c = (int)(i & 127);
    float v = fmaxf(fmaf(Z[i], ab[c], ab[DD + c]), 0.f);
    h[i] = v;
    atomicAdd(&pool[(size_t)gid[r] * (LL * DD) + colOff + c], v);
}

// projection head: out[i] = relu(pool[i] @ pW1 + pb1) @ pW2 + pb2 ; 192 threads/block, block per row
__global__ void proj_kernel(const float* __restrict__ pool, const float* __restrict__ pW1,
                            const float* __restrict__ pb1, const float* __restrict__ pW2,
                            const float* __restrict__ pb2, float* __restrict__ out) {
    __shared__ float row[LL * DD];   // 384
    __shared__ float h1[192];
    int i = blockIdx.x;
    int t = threadIdx.x;
    for (int k = t; k < LL * DD; k += 192) row[k] = pool[(size_t)i * (LL * DD) + k];
    __syncthreads();
    float s = pb1[t];
    for (int k = 0; k < LL * DD; k++) s += row[k] * pW1[(size_t)k * 192 + t];
    h1[t] = fmaxf(s, 0.f);
    __syncthreads();
    if (t < 128) {
        float s2 = pb2[t];
        for (int k = 0; k < 192; k++) s2 += h1[k] * pW2[(size_t)k * 128 + t];
        out[(size_t)i * 128 + t] = s2;
    }
}

__global__ void norms_kernel(const float* __restrict__ p, float* __restrict__ nrm) {
    int row = blockIdx.x, t = threadIdx.x;
    float v = p[(size_t)row * 128 + t];
    v *= v;
    for (int o = 16; o; o >>= 1) v += __shfl_down_sync(0xffffffff, v, o);
    __shared__ float ws[4];
    if ((t & 31) == 0) ws[t >> 5] = v;
    __syncthreads();
    if (t == 0) nrm[row] = sqrtf(ws[0] + ws[1] + ws[2] + ws[3]);
}

// block i computes row i of the similarity matrix and its loss contribution
__global__ void loss_kernel(const float* __restrict__ ch, const float* __restrict__ cm,
                            const float* __restrict__ n_ch, const float* __restrict__ n_cm,
                            float* __restrict__ out) {
    int i = blockIdx.x;
    int t = threadIdx.x;   // 256 threads, one per column j
    __shared__ float sh[128];
    __shared__ float red[256];
    __shared__ float posv;
    if (t < 128) sh[t] = ch[(size_t)i * 128 + t];
    __syncthreads();
    float d = 0.f;
    const float* rowj = cm + (size_t)t * 128;
    for (int k = 0; k < 128; k++) d += sh[k] * rowj[k];
    float s = expf(d / (n_ch[i] * n_cm[t]) * (1.0f / TEMP));
    if (t == i) posv = s;
    red[t] = s;
    __syncthreads();
    for (int o = 128; o; o >>= 1) {
        if (t < o) red[t] += red[t + o];
        __syncthreads();
    }
    if (t == 0) {
        float sum = red[0];
        float li = -logf(posv / (sum - posv));
        atomicAdd(out, li * (1.0f / BB));
    }
}

// ---------------- host orchestration ----------------

static void run_encoder(const float* input, const int* src, const int* dst, const int* gid,
                        const float* W1, const float* g1, const float* b1,
                        const float* W2, const float* g2, const float* b2,
                        float* agg, float* z1, float* z2, float* h,
                        float* stats, float* ab, float* poolSlot) {
    const float* hin = input;
    for (int l = 0; l < LL; l++) {
        cudaMemsetAsync(agg, 0, (size_t)NN * DD * sizeof(float));
        edge_agg<<<(EE * 32 + 255) / 256, 256>>>(hin, src, dst, agg);

        sgemm<0><<<dim3((NN + BM - 1) / BM, HH / BN), 256>>>(hin, agg, W1 + (size_t)l * DD * HH,
                                                             z1, nullptr, NN, DD, HH);
        cudaMemsetAsync(stats, 0, 2 * HH * sizeof(float));
        colstats<<<256, HH>>>(z1, NN, HH, stats);
        ab_kernel<<<1, HH>>>(stats, g1 + l * HH, b1 + l * HH, HH, 1.0f / NN, ab);

        sgemm<1><<<dim3((NN + BM - 1) / BM, DD / BN), 256>>>(z1, nullptr, W2 + (size_t)l * HH * DD,
                                                             z2, ab, NN, HH, DD);
        cudaMemsetAsync(stats, 0, 2 * DD * sizeof(float));
        colstats<<<256, DD>>>(z2, NN, DD, stats);
        ab_kernel<<<1, DD>>>(stats, g2 + l * DD, b2 + l * DD, DD, 1.0f / NN, ab);

        bnrelu_pool<<<((size_t)NN * DD + 255) / 256, 256>>>(z2, ab, gid, h, poolSlot, l * DD);
        hin = h;
    }
}

extern "C" void kernel_launch(void* const* d_in, const int* in_sizes, int n_in,
                              void* d_out, int out_size) {
    const float* feat       = (const float*)d_in[0];
    const int*   src        = (const int*)d_in[1];
    const int*   dst        = (const int*)d_in[2];
    const int*   graph_ids  = (const int*)d_in[3];
    const int*   mask_nodes = (const int*)d_in[4];
    const float* mask_token = (const float*)d_in[5];
    const float* enc_W1 = (const float*)d_in[6];
    const float* enc_g1 = (const float*)d_in[7];
    const float* enc_b1 = (const float*)d_in[8];
    const float* enc_W2 = (const float*)d_in[9];
    const float* enc_g2 = (const float*)d_in[10];
    const float* enc_b2 = (const float*)d_in[11];
    const float* con_W1 = (const float*)d_in[12];
    const float* con_g1 = (const float*)d_in[13];
    const float* con_b1 = (const float*)d_in[14];
    const float* con_W2 = (const float*)d_in[15];
    const float* con_g2 = (const float*)d_in[16];
    const float* con_b2 = (const float*)d_in[17];
    const float* pW1 = (const float*)d_in[18];
    const float* pb1 = (const float*)d_in[19];
    const float* pW2 = (const float*)d_in[20];
    const float* pb2 = (const float*)d_in[21];
    int nMask = in_sizes[4];

    float *x, *h, *agg, *z1, *z2, *pool, *stats, *ab, *p2, *norms;
    cudaGetSymbolAddress((void**)&x, g_x);
    cudaGetSymbolAddress((void**)&h, g_h);
    cudaGetSymbolAddress((void**)&agg, g_agg);
    cudaGetSymbolAddress((void**)&z1, g_z1);
    cudaGetSymbolAddress((void**)&z2, g_z2);
    cudaGetSymbolAddress((void**)&pool, g_pool);
    cudaGetSymbolAddress((void**)&stats, g_stats);
    cudaGetSymbolAddress((void**)&ab, g_ab);
    cudaGetSymbolAddress((void**)&p2, g_p2);
    cudaGetSymbolAddress((void**)&norms, g_norms);

    // masked input
    cudaMemcpyAsync(x, feat, (size_t)NN * DD * sizeof(float), cudaMemcpyDeviceToDevice);
    mask_kernel<<<(nMask * DD + 255) / 256, 256>>>(x, mask_nodes, mask_token, nMask);

    cudaMemsetAsync(pool, 0, 2 * BB * LL * DD * sizeof(float));

    // slot 0: masked input through online encoder -> gh
    run_encoder(x, src, dst, graph_ids, enc_W1, enc_g1, enc_b1, enc_W2, enc_g2, enc_b2,
                agg, z1, z2, h, stats, ab, pool);
    // slot 1: raw features through contrast encoder -> ch
    run_encoder(feat, src, dst, graph_ids, con_W1, con_g1, con_b1, con_W2, con_g2, con_b2,
                agg, z1, z2, h, stats, ab, pool + BB * LL * DD);

    // projection head on both pooled representations
    proj_kernel<<<BB, 192>>>(pool, pW1, pb1, pW2, pb2, p2);                       // c_m (masked)
    proj_kernel<<<BB, 192>>>(pool + BB * LL * DD, pW1, pb1, pW2, pb2, p2 + BB * 128); // c_h (contrast)

    norms_kernel<<<2 * BB, 128>>>(p2, norms);   // rows 0..255: c_m norms, 256..511: c_h norms

    cudaMemsetAsync(d_out, 0, sizeof(float));
    // _cl_loss(c_h, c_m): x = c_h (slot1), x_aug = c_m (slot0)
    loss_kernel<<<BB, 256>>>(p2 + BB * 128, p2, norms + BB, norms, (float*)d_out);
}

// round 2
// speedup vs baseline: 1.6694x; 1.6694x over previous
#include <cuda_runtime.h>
#include <cuda_bf16.h>
#include <math.h>

#define NN 50000
#define EE 800000
#define BB 256
#define DD 128
#define HH 256
#define LL 3
#define TEMP 0.2f
#define BN_EPS 1e-5f

// ---------------- scratch (device globals) ----------------
__device__ __align__(16) float g_x[(size_t)NN * DD];
__device__ __align__(16) float g_h[(size_t)NN * DD];
__device__ __align__(16) float g_agg[(size_t)NN * DD];
__device__ __align__(16) float g_z1[(size_t)NN * HH];
__device__ __align__(16) float g_z2[(size_t)NN * DD];
__device__ __align__(16) float g_pool[2 * BB * LL * DD];
__device__ __align__(16) float g_stats[2 * HH];
__device__ __align__(16) float g_ab[2 * HH];
__device__ __align__(16) float g_p2[2 * BB * 128];
__device__ float g_norms[2 * BB];

// ---------------- helpers ----------------
__device__ __forceinline__ void red_add_v4(float* p, float4 v) {
    asm volatile("red.global.add.v4.f32 [%0], {%1,%2,%3,%4};"
                 :: "l"(p), "f"(v.x), "f"(v.y), "f"(v.z), "f"(v.w) : "memory");
}

// ---------------- kernels ----------------

__global__ void mask_kernel(float* __restrict__ x, const int* __restrict__ idx,
                            const float* __restrict__ tok, int nMask) {
    int i = blockIdx.x * blockDim.x + threadIdx.x;
    if (i >= nMask * DD) return;
    int m = i >> 7, c = i & 127;
    x[(size_t)idx[m] * DD + c] = tok[c];
}

// agg[dst] += h[src]; warp per edge, float4 per lane, vector RED
__global__ void edge_agg(const float* __restrict__ hin, const int* __restrict__ src,
                         const int* __restrict__ dst, float* __restrict__ agg) {
    int idx = blockIdx.x * blockDim.x + threadIdx.x;
    int e = idx >> 5;
    if (e >= EE) return;
    int lane = idx & 31;
    int s = __ldg(src + e), d = __ldg(dst + e);
    float4 v = *reinterpret_cast<const float4*>(hin + (size_t)s * DD + lane * 4);
    red_add_v4(agg + (size_t)d * DD + lane * 4, v);
}

// ---------------- fused GEMM: C = f(A) @ B, epilogue col-sum/sumsq -> stats ----
// MODE 0: f(A) = A                 (agg already holds h+agg)
// MODE 1: f(A) = relu(A*a[k]+c[k]) (BN1+ReLU fused into A read)
#define BM 128
#define BNC 128
#define BK 16

template <int MODE>
__global__ __launch_bounds__(256, 2)
void gemm128(const float* __restrict__ A, const float* __restrict__ Bm,
             float* __restrict__ C, float* __restrict__ stats,
             const float* __restrict__ ab, int M, int K, int Ncols) {
    __shared__ __align__(16) float As[BK][BM];
    __shared__ __align__(16) float Bs[BK][BNC];
    __shared__ float ssum[BNC], ssq[BNC];

    const int bm = blockIdx.x * BM;
    const int bn = blockIdx.y * BNC;
    const int t = threadIdx.x;          // 0..255
    const int tx = t & 15, ty = t >> 4;

    // A load mapping: row = t>>1 (0..127), k-offset = (t&1)*8 (two float4)
    const int arow = t >> 1;
    const int ak = (t & 1) * 8;
    // B load mapping: krow = t>>4 (0..15), col-offset = (t&15)*8
    const int bk = t >> 4;
    const int bcol = (t & 15) * 8;

    float acc[8][8];
#pragma unroll
    for (int i = 0; i < 8; i++)
#pragma unroll
        for (int j = 0; j < 8; j++) acc[i][j] = 0.f;

    const int row = bm + arow;
    const bool rok = (row < M);
    const float* Arow = A + (size_t)row * K;

    float4 na0, na1, nb0, nb1;

    // prologue load k0 = 0
    {
        if (rok) {
            na0 = *reinterpret_cast<const float4*>(Arow + ak);
            na1 = *reinterpret_cast<const float4*>(Arow + ak + 4);
            if (MODE == 1) {
                float4 sa0 = *reinterpret_cast<const float4*>(ab + ak);
                float4 sc0 = *reinterpret_cast<const float4*>(ab + K + ak);
                float4 sa1 = *reinterpret_cast<const float4*>(ab + ak + 4);
                float4 sc1 = *reinterpret_cast<const float4*>(ab + K + ak + 4);
                na0.x = fmaxf(fmaf(na0.x, sa0.x, sc0.x), 0.f);
                na0.y = fmaxf(fmaf(na0.y, sa0.y, sc0.y), 0.f);
                na0.z = fmaxf(fmaf(na0.z, sa0.z, sc0.z), 0.f);
                na0.w = fmaxf(fmaf(na0.w, sa0.w, sc0.w), 0.f);
                na1.x = fmaxf(fmaf(na1.x, sa1.x, sc1.x), 0.f);
                na1.y = fmaxf(fmaf(na1.y, sa1.y, sc1.y), 0.f);
                na1.z = fmaxf(fmaf(na1.z, sa1.z, sc1.z), 0.f);
                na1.w = fmaxf(fmaf(na1.w, sa1.w, sc1.w), 0.f);
            }
        } else {
            na0 = na1 = make_float4(0.f, 0.f, 0.f, 0.f);
        }
        nb0 = *reinterpret_cast<const float4*>(Bm + (size_t)bk * Ncols + bn + bcol);
        nb1 = *reinterpret_cast<const float4*>(Bm + (size_t)bk * Ncols + bn + bcol + 4);
    }

    for (int k0 = 0; k0 < K; k0 += BK) {
        // commit staged tile to smem
        As[ak + 0][arow] = na0.x; As[ak + 1][arow] = na0.y;
        As[ak + 2][arow] = na0.z; As[ak + 3][arow] = na0.w;
        As[ak + 4][arow] = na1.x; As[ak + 5][arow] = na1.y;
        As[ak + 6][arow] = na1.z; As[ak + 7][arow] = na1.w;
        *reinterpret_cast<float4*>(&Bs[bk][bcol]) = nb0;
        *reinterpret_cast<float4*>(&Bs[bk][bcol + 4]) = nb1;
        __syncthreads();

        // stage next tile
        float4 ta0, ta1, tb0, tb1;
        const int kn = k0 + BK;
        if (kn < K) {
            if (rok) {
                ta0 = *reinterpret_cast<const float4*>(Arow + kn + ak);
                ta1 = *reinterpret_cast<const float4*>(Arow + kn + ak + 4);
                if (MODE == 1) {
                    float4 sa0 = *reinterpret_cast<const float4*>(ab + kn + ak);
                    float4 sc0 = *reinterpret_cast<const float4*>(ab + K + kn + ak);
                    float4 sa1 = *reinterpret_cast<const float4*>(ab + kn + ak + 4);
                    float4 sc1 = *reinterpret_cast<const float4*>(ab + K + kn + ak + 4);
                    ta0.x = fmaxf(fmaf(ta0.x, sa0.x, sc0.x), 0.f);
                    ta0.y = fmaxf(fmaf(ta0.y, sa0.y, sc0.y), 0.f);
                    ta0.z = fmaxf(fmaf(ta0.z, sa0.z, sc0.z), 0.f);
                    ta0.w = fmaxf(fmaf(ta0.w, sa0.w, sc0.w), 0.f);
                    ta1.x = fmaxf(fmaf(ta1.x, sa1.x, sc1.x), 0.f);
                    ta1.y = fmaxf(fmaf(ta1.y, sa1.y, sc1.y), 0.f);
                    ta1.z = fmaxf(fmaf(ta1.z, sa1.z, sc1.z), 0.f);
                    ta1.w = fmaxf(fmaf(ta1.w, sa1.w, sc1.w), 0.f);
                }
            } else {
                ta0 = ta1 = make_float4(0.f, 0.f, 0.f, 0.f);
            }
            tb0 = *reinterpret_cast<const float4*>(Bm + (size_t)(kn + bk) * Ncols + bn + bcol);
            tb1 = *reinterpret_cast<const float4*>(Bm + (size_t)(kn + bk) * Ncols + bn + bcol + 4);
        }

        // compute on current smem tiles
#pragma unroll
        for (int k = 0; k < BK; k++) {
            float4 a0 = *reinterpret_cast<const float4*>(&As[k][ty * 4]);
            float4 a1 = *reinterpret_cast<const float4*>(&As[k][64 + ty * 4]);
            float4 b0 = *reinterpret_cast<const float4*>(&Bs[k][tx * 4]);
            float4 b1 = *reinterpret_cast<const float4*>(&Bs[k][64 + tx * 4]);
            float av[8] = {a0.x, a0.y, a0.z, a0.w, a1.x, a1.y, a1.z, a1.w};
            float bv[8] = {b0.x, b0.y, b0.z, b0.w, b1.x, b1.y, b1.z, b1.w};
#pragma unroll
            for (int i = 0; i < 8; i++)
#pragma unroll
                for (int j = 0; j < 8; j++)
                    acc[i][j] = fmaf(av[i], bv[j], acc[i][j]);
        }
        __syncthreads();
        na0 = ta0; na1 = ta1; nb0 = tb0; nb1 = tb1;
    }

    // write C
#pragma unroll
    for (int half = 0; half < 2; half++) {
#pragma unroll
        for (int i = 0; i < 4; i++) {
            int r = bm + half * 64 + ty * 4 + i;
            if (r < M) {
                float* Crow = C + (size_t)r * Ncols + bn;
                int ai = half * 4 + i;
                *reinterpret_cast<float4*>(Crow + tx * 4) =
                    make_float4(acc[ai][0], acc[ai][1], acc[ai][2], acc[ai][3]);
                *reinterpret_cast<float4*>(Crow + 64 + tx * 4) =
                    make_float4(acc[ai][4], acc[ai][5], acc[ai][6], acc[ai][7]);
            }
        }
    }

    // epilogue: per-block column sum / sumsq (padded rows contribute 0)
    if (t < BNC) { ssum[t] = 0.f; ssq[t] = 0.f; }
    __syncthreads();
#pragma unroll
    for (int j = 0; j < 8; j++) {
        int col = (j < 4) ? (tx * 4 + j) : (64 + tx * 4 + (j - 4));
        float s = 0.f, q = 0.f;
#pragma unroll
        for (int i = 0; i < 8; i++) {
            float v = acc[i][j];
            s += v;
            q = fmaf(v, v, q);
        }
        atomicAdd(&ssum[col], s);
        atomicAdd(&ssq[col], q);
    }
    __syncthreads();
    if (t < BNC) {
        atomicAdd(&stats[bn + t], ssum[t]);
        atomicAdd(&stats[Ncols + bn + t], ssq[t]);
    }
}

__global__ void ab_kernel(const float* __restrict__ stats, const float* __restrict__ g,
                          const float* __restrict__ b, int C, float invM, float* __restrict__ ab) {
    int t = threadIdx.x;
    if (t < C) {
        float m = stats[t] * invM;
        float var = stats[C + t] * invM - m * m;
        float a = g[t] * rsqrtf(var + BN_EPS);
        ab[t] = a;
        ab[C + t] = b[t] - m * a;
    }
}

// h = relu(bn(z2)); also duplicate into agg (pre-init for next layer's edge_agg);
// pool[gid, colOff+c] += h  (vector RED)
__global__ void bnrelu_pool(const float* __restrict__ Z, const float* __restrict__ ab,
                            const int* __restrict__ gid, float* __restrict__ h,
                            float* __restrict__ agg, float* __restrict__ pool, int colOff) {
    int idx = blockIdx.x * blockDim.x + threadIdx.x;   // one float4 per thread
    if (idx >= NN * DD / 4) return;
    int r = idx >> 5;          // 32 float4 per row
    int c = (idx & 31) * 4;
    float4 z = *reinterpret_cast<const float4*>(Z + (size_t)idx * 4);
    float4 sa = *reinterpret_cast<const float4*>(ab + c);
    float4 sc = *reinterpret_cast<const float4*>(ab + DD + c);
    float4 v;
    v.x = fmaxf(fmaf(z.x, sa.x, sc.x), 0.f);
    v.y = fmaxf(fmaf(z.y, sa.y, sc.y), 0.f);
    v.z = fmaxf(fmaf(z.z, sa.z, sc.z), 0.f);
    v.w = fmaxf(fmaf(z.w, sa.w, sc.w), 0.f);
    *reinterpret_cast<float4*>(h + (size_t)idx * 4) = v;
    *reinterpret_cast<float4*>(agg + (size_t)idx * 4) = v;
    red_add_v4(&pool[(size_t)gid[r] * (LL * DD) + colOff + c], v);
}

// projection head
__global__ void proj_kernel(const float* __restrict__ pool, const float* __restrict__ pW1,
                            const float* __restrict__ pb1, const float* __restrict__ pW2,
                            const float* __restrict__ pb2, float* __restrict__ out) {
    __shared__ float row[LL * DD];
    __shared__ float h1[192];
    int i = blockIdx.x;
    int t = threadIdx.x;
    for (int k = t; k < LL * DD; k += 192) row[k] = pool[(size_t)i * (LL * DD) + k];
    __syncthreads();
    float s = pb1[t];
    for (int k = 0; k < LL * DD; k++) s += row[k] * pW1[(size_t)k * 192 + t];
    h1[t] = fmaxf(s, 0.f);
    __syncthreads();
    if (t < 128) {
        float s2 = pb2[t];
        for (int k = 0; k < 192; k++) s2 += h1[k] * pW2[(size_t)k * 128 + t];
        out[(size_t)i * 128 + t] = s2;
    }
}

__global__ void norms_kernel(const float* __restrict__ p, float* __restrict__ nrm) {
    int row = blockIdx.x, t = threadIdx.x;
    float v = p[(size_t)row * 128 + t];
    v *= v;
    for (int o = 16; o; o >>= 1) v += __shfl_down_sync(0xffffffff, v, o);
    __shared__ float ws[4];
    if ((t & 31) == 0) ws[t >> 5] = v;
    __syncthreads();
    if (t == 0) nrm[row] = sqrtf(ws[0] + ws[1] + ws[2] + ws[3]);
}

__global__ void loss_kernel(const float* __restrict__ ch, const float* __restrict__ cm,
                            const float* __restrict__ n_ch, const float* __restrict__ n_cm,
                            float* __restrict__ out) {
    int i = blockIdx.x;
    int t = threadIdx.x;
    __shared__ float sh[128];
    __shared__ float red[256];
    __shared__ float posv;
    if (t < 128) sh[t] = ch[(size_t)i * 128 + t];
    __syncthreads();
    float d = 0.f;
    const float* rowj = cm + (size_t)t * 128;
    for (int k = 0; k < 128; k++) d += sh[k] * rowj[k];
    float s = expf(d / (n_ch[i] * n_cm[t]) * (1.0f / TEMP));
    if (t == i) posv = s;
    red[t] = s;
    __syncthreads();
    for (int o = 128; o; o >>= 1) {
        if (t < o) red[t] += red[t + o];
        __syncthreads();
    }
    if (t == 0) {
        float sum = red[0];
        float li = -logf(posv / (sum - posv));
        atomicAdd(out, li * (1.0f / BB));
    }
}

// ---------------- host orchestration ----------------

static void run_encoder(const float* input, const int* src, const int* dst, const int* gid,
                        const float* W1, const float* g1, const float* b1,
                        const float* W2, const float* g2, const float* b2,
                        float* agg, float* z1, float* z2, float* h,
                        float* stats, float* ab, float* poolSlot) {
    for (int l = 0; l < LL; l++) {
        if (l == 0)
            cudaMemcpyAsync(agg, input, (size_t)NN * DD * sizeof(float), cudaMemcpyDeviceToDevice);
        // else: agg pre-initialized to h by previous bnrelu_pool
        edge_agg<<<(EE * 32 + 255) / 256, 256>>>(l == 0 ? input : h, src, dst, agg);

        cudaMemsetAsync(stats, 0, 2 * HH * sizeof(float));
        gemm128<0><<<dim3((NN + BM - 1) / BM, HH / BNC), 256>>>(
            agg, W1 + (size_t)l * DD * HH, z1, stats, nullptr, NN, DD, HH);
        ab_kernel<<<1, HH>>>(stats, g1 + l * HH, b1 + l * HH, HH, 1.0f / NN, ab);

        cudaMemsetAsync(stats, 0, 2 * DD * sizeof(float));
        gemm128<1><<<dim3((NN + BM - 1) / BM, DD / BNC), 256>>>(
            z1, W2 + (size_t)l * HH * DD, z2, stats, ab, NN, HH, DD);
        ab_kernel<<<1, DD>>>(stats, g2 + l * DD, b2 + l * DD, DD, 1.0f / NN, ab);

        bnrelu_pool<<<(NN * DD / 4 + 255) / 256, 256>>>(z2, ab, gid, h, agg, poolSlot, l * DD);
    }
}

extern "C" void kernel_launch(void* const* d_in, const int* in_sizes, int n_in,
                              void* d_out, int out_size) {
    const float* feat       = (const float*)d_in[0];
    const int*   src        = (const int*)d_in[1];
    const int*   dst        = (const int*)d_in[2];
    const int*   graph_ids  = (const int*)d_in[3];
    const int*   mask_nodes = (const int*)d_in[4];
    const float* mask_token = (const float*)d_in[5];
    const float* enc_W1 = (const float*)d_in[6];
    const float* enc_g1 = (const float*)d_in[7];
    const float* enc_b1 = (const float*)d_in[8];
    const float* enc_W2 = (const float*)d_in[9];
    const float* enc_g2 = (const float*)d_in[10];
    const float* enc_b2 = (const float*)d_in[11];
    const float* con_W1 = (const float*)d_in[12];
    const float* con_g1 = (const float*)d_in[13];
    const float* con_b1 = (const float*)d_in[14];
    const float* con_W2 = (const float*)d_in[15];
    const float* con_g2 = (const float*)d_in[16];
    const float* con_b2 = (const float*)d_in[17];
    const float* pW1 = (const float*)d_in[18];
    const float* pb1 = (const float*)d_in[19];
    const float* pW2 = (const float*)d_in[20];
    const float* pb2 = (const float*)d_in[21];
    int nMask = in_sizes[4];

    float *x, *h, *agg, *z1, *z2, *pool, *stats, *ab, *p2, *norms;
    cudaGetSymbolAddress((void**)&x, g_x);
    cudaGetSymbolAddress((void**)&h, g_h);
    cudaGetSymbolAddress((void**)&agg, g_agg);
    cudaGetSymbolAddress((void**)&z1, g_z1);
    cudaGetSymbolAddress((void**)&z2, g_z2);
    cudaGetSymbolAddress((void**)&pool, g_pool);
    cudaGetSymbolAddress((void**)&stats, g_stats);
    cudaGetSymbolAddress((void**)&ab, g_ab);
    cudaGetSymbolAddress((void**)&p2, g_p2);
    cudaGetSymbolAddress((void**)&norms, g_norms);

    cudaMemcpyAsync(x, feat, (size_t)NN * DD * sizeof(float), cudaMemcpyDeviceToDevice);
    mask_kernel<<<(nMask * DD + 255) / 256, 256>>>(x, mask_nodes, mask_token, nMask);

    cudaMemsetAsync(pool, 0, 2 * BB * LL * DD * sizeof(float));

    run_encoder(x, src, dst, graph_ids, enc_W1, enc_g1, enc_b1, enc_W2, enc_g2, enc_b2,
                agg, z1, z2, h, stats, ab, pool);
    run_encoder(feat, src, dst, graph_ids, con_W1, con_g1, con_b1, con_W2, con_g2, con_b2,
                agg, z1, z2, h, stats, ab, pool + BB * LL * DD);

    proj_kernel<<<BB, 192>>>(pool, pW1, pb1, pW2, pb2, p2);
    proj_kernel<<<BB, 192>>>(pool + BB * LL * DD, pW1, pb1, pW2, pb2, p2 + BB * 128);

    norms_kernel<<<2 * BB, 128>>>(p2, norms);

    cudaMemsetAsync(d_out, 0, sizeof(float));
    loss_kernel<<<BB, 256>>>(p2 + BB * 128, p2, norms + BB, norms, (float*)d_out);
}

// round 4
// speedup vs baseline: 1.7826x; 1.0678x over previous
#include <cuda_runtime.h>
#include <cuda_bf16.h>
#include <math.h>
#include <stdint.h>

#define NN 50000
#define EE 800000
#define BB 256
#define DD 128
#define HH 256
#define LL 3
#define TEMP 0.2f
#define BN_EPS 1e-5f

// ---------------- scratch (device globals) ----------------
__device__ __align__(16) float g_x[(size_t)NN * DD];
__device__ __align__(16) float g_h[(size_t)NN * DD];
__device__ __align__(16) float g_agg[(size_t)NN * DD];
__device__ __align__(16) float g_z1[(size_t)NN * HH];
__device__ __align__(16) float g_z2[(size_t)NN * DD];
__device__ __align__(16) float g_pool[2 * BB * LL * DD];
__device__ __align__(16) float g_stats[2 * HH];
__device__ __align__(16) float g_ab[2 * HH];
__device__ __align__(16) float g_p2[2 * BB * 128];
__device__ float g_norms[2 * BB];
// transposed/split weights: W1T [enc][L][HH][DD], W2T [enc][L][DD][HH]
__device__ __align__(16) float g_W1T_hi[2 * LL * HH * DD];
__device__ __align__(16) float g_W1T_lo[2 * LL * HH * DD];
__device__ __align__(16) float g_W2T_hi[2 * LL * DD * HH];
__device__ __align__(16) float g_W2T_lo[2 * LL * DD * HH];

// ---------------- helpers ----------------
__device__ __forceinline__ float tf32_round(float x) {
    uint32_t u;
    asm("cvt.rna.tf32.f32 %0, %1;" : "=r"(u) : "f"(x));
    return __uint_as_float(u);
}
__device__ __forceinline__ void red_add_v4(float* p, float4 v) {
    asm volatile("red.global.add.v4.f32 [%0], {%1,%2,%3,%4};"
                 :: "l"(p), "f"(v.x), "f"(v.y), "f"(v.z), "f"(v.w) : "memory");
}
__device__ __forceinline__ void mma_tf32(float* c, const uint32_t* a, const uint32_t* b) {
    asm volatile(
        "mma.sync.aligned.m16n8k8.row.col.f32.tf32.tf32.f32 "
        "{%0,%1,%2,%3}, {%4,%5,%6,%7}, {%8,%9}, {%0,%1,%2,%3};"
        : "+f"(c[0]), "+f"(c[1]), "+f"(c[2]), "+f"(c[3])
        : "r"(a[0]), "r"(a[1]), "r"(a[2]), "r"(a[3]), "r"(b[0]), "r"(b[1]));
}

// ---------------- small kernels ----------------

__global__ void mask_kernel(float* __restrict__ x, const int* __restrict__ idx,
                            const float* __restrict__ tok, int nMask) {
    int i = blockIdx.x * blockDim.x + threadIdx.x;
    if (i >= nMask * DD) return;
    int m = i >> 7, c = i & 127;
    x[(size_t)idx[m] * DD + c] = tok[c];
}

__global__ void edge_agg(const float* __restrict__ hin, const int* __restrict__ src,
                         const int* __restrict__ dst, float* __restrict__ agg) {
    int idx = blockIdx.x * blockDim.x + threadIdx.x;
    int e = idx >> 5;
    if (e >= EE) return;
    int lane = idx & 31;
    int s = __ldg(src + e), d = __ldg(dst + e);
    float4 v = *reinterpret_cast<const float4*>(hin + (size_t)s * DD + lane * 4);
    red_add_v4(agg + (size_t)d * DD + lane * 4, v);
}

__global__ void ab_kernel(const float* __restrict__ stats, const float* __restrict__ g,
                          const float* __restrict__ b, int C, float invM, float* __restrict__ ab) {
    int t = threadIdx.x;
    if (t < C) {
        float m = stats[t] * invM;
        float var = stats[C + t] * invM - m * m;
        float a = g[t] * rsqrtf(var + BN_EPS);
        ab[t] = a;
        ab[C + t] = b[t] - m * a;
    }
}

__global__ void bnrelu_pool(const float* __restrict__ Z, const float* __restrict__ ab,
                            const int* __restrict__ gid, float* __restrict__ h,
                            float* __restrict__ agg, float* __restrict__ pool, int colOff) {
    int idx = blockIdx.x * blockDim.x + threadIdx.x;
    if (idx >= NN * DD / 4) return;
    int r = idx >> 5;
    int c = (idx & 31) * 4;
    float4 z = *reinterpret_cast<const float4*>(Z + (size_t)idx * 4);
    float4 sa = *reinterpret_cast<const float4*>(ab + c);
    float4 sc = *reinterpret_cast<const float4*>(ab + DD + c);
    float4 v;
    v.x = fmaxf(fmaf(z.x, sa.x, sc.x), 0.f);
    v.y = fmaxf(fmaf(z.y, sa.y, sc.y), 0.f);
    v.z = fmaxf(fmaf(z.z, sa.z, sc.z), 0.f);
    v.w = fmaxf(fmaf(z.w, sa.w, sc.w), 0.f);
    *reinterpret_cast<float4*>(h + (size_t)idx * 4) = v;
    *reinterpret_cast<float4*>(agg + (size_t)idx * 4) = v;
    red_add_v4(&pool[(size_t)gid[r] * (LL * DD) + colOff + c], v);
}

__global__ void proj_kernel(const float* __restrict__ pool, const float* __restrict__ pW1,
                            const float* __restrict__ pb1, const float* __restrict__ pW2,
                            const float* __restrict__ pb2, float* __restrict__ out) {
    __shared__ float row[LL * DD];
    __shared__ float h1[192];
    int i = blockIdx.x;
    int t = threadIdx.x;
    for (int k = t; k < LL * DD; k += 192) row[k] = pool[(size_t)i * (LL * DD) + k];
    __syncthreads();
    float s = pb1[t];
    for (int k = 0; k < LL * DD; k++) s += row[k] * pW1[(size_t)k * 192 + t];
    h1[t] = fmaxf(s, 0.f);
    __syncthreads();
    if (t < 128) {
        float s2 = pb2[t];
        for (int k = 0; k < 192; k++) s2 += h1[k] * pW2[(size_t)k * 128 + t];
        out[(size_t)i * 128 + t] = s2;
    }
}

__global__ void norms_kernel(const float* __restrict__ p, float* __restrict__ nrm) {
    int row = blockIdx.x, t = threadIdx.x;
    float v = p[(size_t)row * 128 + t];
    v *= v;
    for (int o = 16; o; o >>= 1) v += __shfl_down_sync(0xffffffff, v, o);
    __shared__ float ws[4];
    if ((t & 31) == 0) ws[t >> 5] = v;
    __syncthreads();
    if (t == 0) nrm[row] = sqrtf(ws[0] + ws[1] + ws[2] + ws[3]);
}

__global__ void loss_kernel(const float* __restrict__ ch, const float* __restrict__ cm,
                            const float* __restrict__ n_ch, const float* __restrict__ n_cm,
                            float* __restrict__ out) {
    int i = blockIdx.x;
    int t = threadIdx.x;
    __shared__ float sh[128];
    __shared__ float red[256];
    __shared__ float posv;
    if (t < 128) sh[t] = ch[(size_t)i * 128 + t];
    __syncthreads();
    float d = 0.f;
    const float* rowj = cm + (size_t)t * 128;
    for (int k = 0; k < 128; k++) d += sh[k] * rowj[k];
    float s = expf(d / (n_ch[i] * n_cm[t]) * (1.0f / TEMP));
    if (t == i) posv = s;
    red[t] = s;
    __syncthreads();
    for (int o = 128; o; o >>= 1) {
        if (t < o) red[t] += red[t + o];
        __syncthreads();
    }
    if (t == 0) {
        float sum = red[0];
        float li = -logf(posv / (sum - posv));
        atomicAdd(out, li * (1.0f / BB));
    }
}

// weight prep: [L, K, N] -> transposed hi/lo [L, N, K]
__global__ void tsplit(const float* __restrict__ W, float* __restrict__ hi,
                       float* __restrict__ lo, int K, int N, int total) {
    int i = blockIdx.x * blockDim.x + threadIdx.x;
    if (i >= total) return;
    int l = i / (K * N), rem = i % (K * N);
    int k = rem / N, n = rem % N;
    float v = W[i];
    float h = tf32_round(v);
    size_t o = (size_t)l * K * N + (size_t)n * K + k;
    hi[o] = h;
    lo[o] = v - h;
}

// ---------------- 3xTF32 mma.sync GEMM with fused BN-stats epilogue -----------
// C[M, NT] = f(A)[M, KT] @ B^T, B stored [NT, KT] pre-split hi/lo.
// MODE 0: f(A)=A.  MODE 1: f(A)=relu(A*ab[k]+ab[KT+k]).
// CTA tile 128x128, 8 warps (2 Mwarps x 4 Nwarps), warp tile 64x32.
// smem: padded stride 36 floats -> conflict-free m16n8k8 fragment loads.

#define PAD 36
#define GEMM_SMEM (4 * 128 * PAD * 4)   // 73728 B

template <int MODE, int NT, int KT>
__global__ __launch_bounds__(256, 1)
void gemm_mma(const float* __restrict__ A, const float* __restrict__ Bh,
              const float* __restrict__ Bl, float* __restrict__ C,
              float* __restrict__ stats, const float* __restrict__ ab, int M) {
    extern __shared__ float sm[];
    float* Ahs = sm;                       // [128][PAD]
    float* Als = Ahs + 128 * PAD;
    float* Bhs = Als + 128 * PAD;          // [128][PAD]
    float* Bls = Bhs + 128 * PAD;
    __shared__ float ssum[128], ssq[128];

    const int tid = threadIdx.x;
    const int lane = tid & 31, w = tid >> 5;
    const int mw = w >> 2, nw = w & 3;     // 2 x 4 warp grid
    const int bm = blockIdx.x * 128, bn = blockIdx.y * 128;

    float acc[4][4][4];
#pragma unroll
    for (int mi = 0; mi < 4; mi++)
#pragma unroll
        for (int ni = 0; ni < 4; ni++)
#pragma unroll
            for (int r = 0; r < 4; r++) acc[mi][ni][r] = 0.f;

    const int lrow = tid >> 1;
    const int lcol0 = (tid & 1) * 16;
    const bool rok = (bm + lrow) < M;
    const float* Arow = A + (size_t)(bm + lrow) * KT;
    const float* Bhrow = Bh + (size_t)(bn + lrow) * KT;
    const float* Blrow = Bl + (size_t)(bn + lrow) * KT;

    const int frow = lane >> 2;            // fragment row group
    const int fcol = lane & 3;             // fragment col-in-group

    for (int k0 = 0; k0 < KT; k0 += 32) {
        // ---- stage A (split hi/lo) ----
#pragma unroll
        for (int i = 0; i < 4; i++) {
            int col = lcol0 + i * 4;
            float4 v = make_float4(0.f, 0.f, 0.f, 0.f);
            if (rok) {
                v = *reinterpret_cast<const float4*>(Arow + k0 + col);
                if (MODE == 1) {
                    float4 sa = *reinterpret_cast<const float4*>(ab + k0 + col);
                    float4 sc = *reinterpret_cast<const float4*>(ab + KT + k0 + col);
                    v.x = fmaxf(fmaf(v.x, sa.x, sc.x), 0.f);
                    v.y = fmaxf(fmaf(v.y, sa.y, sc.y), 0.f);
                    v.z = fmaxf(fmaf(v.z, sa.z, sc.z), 0.f);
                    v.w = fmaxf(fmaf(v.w, sa.w, sc.w), 0.f);
                }
            }
            float4 hi = make_float4(tf32_round(v.x), tf32_round(v.y),
                                    tf32_round(v.z), tf32_round(v.w));
            float* ph = Ahs + lrow * PAD + col;
            float* pl = Als + lrow * PAD + col;
            ph[0] = hi.x; ph[1] = hi.y; ph[2] = hi.z; ph[3] = hi.w;
            pl[0] = v.x - hi.x; pl[1] = v.y - hi.y; pl[2] = v.z - hi.z; pl[3] = v.w - hi.w;
        }
        // ---- stage B (pre-split) ----
#pragma unroll
        for (int i = 0; i < 4; i++) {
            int col = lcol0 + i * 4;
            float4 vh = *reinterpret_cast<const float4*>(Bhrow + k0 + col);
            float4 vl = *reinterpret_cast<const float4*>(Blrow + k0 + col);
            float* ph = Bhs + lrow * PAD + col;
            float* pl = Bls + lrow * PAD + col;
            ph[0] = vh.x; ph[1] = vh.y; ph[2] = vh.z; ph[3] = vh.w;
            pl[0] = vl.x; pl[1] = vl.y; pl[2] = vl.z; pl[3] = vl.w;
        }
        __syncthreads();

#pragma unroll
        for (int kk = 0; kk < 4; kk++) {
            const int k = kk * 8;
            uint32_t afh[4][4], afl[4][4];
#pragma unroll
            for (int mi = 0; mi < 4; mi++) {
                int r0 = mw * 64 + mi * 16 + frow;
                int c0 = k + fcol;
                afh[mi][0] = __float_as_uint(Ahs[r0 * PAD + c0]);
                afh[mi][1] = __float_as_uint(Ahs[(r0 + 8) * PAD + c0]);
                afh[mi][2] = __float_as_uint(Ahs[r0 * PAD + c0 + 4]);
                afh[mi][3] = __float_as_uint(Ahs[(r0 + 8) * PAD + c0 + 4]);
                afl[mi][0] = __float_as_uint(Als[r0 * PAD + c0]);
                afl[mi][1] = __float_as_uint(Als[(r0 + 8) * PAD + c0]);
                afl[mi][2] = __float_as_uint(Als[r0 * PAD + c0 + 4]);
                afl[mi][3] = __float_as_uint(Als[(r0 + 8) * PAD + c0 + 4]);
            }
            uint32_t bfh[4][2], bfl[4][2];
#pragma unroll
            for (int ni = 0; ni < 4; ni++) {
                int n0 = nw * 32 + ni * 8 + frow;
                int kb = k + fcol;
                bfh[ni][0] = __float_as_uint(Bhs[n0 * PAD + kb]);
                bfh[ni][1] = __float_as_uint(Bhs[n0 * PAD + kb + 4]);
                bfl[ni][0] = __float_as_uint(Bls[n0 * PAD + kb]);
                bfl[ni][1] = __float_as_uint(Bls[n0 * PAD + kb + 4]);
            }
#pragma unroll
            for (int mi = 0; mi < 4; mi++)
#pragma unroll
                for (int ni = 0; ni < 4; ni++) {
                    mma_tf32(acc[mi][ni], afh[mi], bfh[ni]);
                    mma_tf32(acc[mi][ni], afh[mi], bfl[ni]);
                    mma_tf32(acc[mi][ni], afl[mi], bfh[ni]);
                }
        }
        __syncthreads();
    }

    // ---- epilogue: C store + fused column stats ----
    if (tid < 128) { ssum[tid] = 0.f; ssq[tid] = 0.f; }
    __syncthreads();

#pragma unroll
    for (int mi = 0; mi < 4; mi++) {
#pragma unroll
        for (int ni = 0; ni < 4; ni++) {
            int row = bm + mw * 64 + mi * 16 + frow;
            int coll = nw * 32 + ni * 8 + 2 * fcol;
            float* a = acc[mi][ni];
            if (row < M)
                *reinterpret_cast<float2*>(C + (size_t)row * NT + bn + coll) =
                    make_float2(a[0], a[1]);
            if (row + 8 < M)
                *reinterpret_cast<float2*>(C + (size_t)(row + 8) * NT + bn + coll) =
                    make_float2(a[2], a[3]);
        }
    }

    // stats: per (ni, col pair) sum over mi, reduce over row groups via shfl
#pragma unroll
    for (int ni = 0; ni < 4; ni++) {
        float s0 = 0.f, s1 = 0.f, q0 = 0.f, q1 = 0.f;
#pragma unroll
        for (int mi = 0; mi < 4; mi++) {
            float* a = acc[mi][ni];
            s0 += a[0] + a[2];
            s1 += a[1] + a[3];
            q0 += a[0] * a[0] + a[2] * a[2];
            q1 += a[1] * a[1] + a[3] * a[3];
        }
#pragma unroll
        for (int off = 4; off < 32; off <<= 1) {
            s0 += __shfl_xor_sync(0xffffffff, s0, off);
            s1 += __shfl_xor_sync(0xffffffff, s1, off);
            q0 += __shfl_xor_sync(0xffffffff, q0, off);
            q1 += __shfl_xor_sync(0xffffffff, q1, off);
        }
        if (lane < 4) {
            int coll = nw * 32 + ni * 8 + 2 * fcol;
            atomicAdd(&ssum[coll], s0);
            atomicAdd(&ssum[coll + 1], s1);
            atomicAdd(&ssq[coll], q0);
            atomicAdd(&ssq[coll + 1], q1);
        }
    }
    __syncthreads();
    if (tid < 128) {
        atomicAdd(&stats[bn + tid], ssum[tid]);
        atomicAdd(&stats[NT + bn + tid], ssq[tid]);
    }
}

// ---------------- host orchestration ----------------

static void run_encoder(const float* input, const int* src, const int* dst, const int* gid,
                        const float* W1Th, const float* W1Tl,
                        const float* W2Th, const float* W2Tl,
                        const float* g1, const float* b1,
                        const float* g2, const float* b2,
                        float* agg, float* z1, float* z2, float* h,
                        float* stats, float* ab, float* poolSlot) {
    const int GB = (NN + 127) / 128;   // 391
    for (int l = 0; l < LL; l++) {
        if (l == 0)
            cudaMemcpyAsync(agg, input, (size_t)NN * DD * sizeof(float), cudaMemcpyDeviceToDevice);
        edge_agg<<<(EE * 32 + 255) / 256, 256>>>(l == 0 ? input : h, src, dst, agg);

        cudaMemsetAsync(stats, 0, 2 * HH * sizeof(float));
        gemm_mma<0, HH, DD><<<dim3(GB, HH / 128), 256, GEMM_SMEM>>>(
            agg, W1Th + (size_t)l * HH * DD, W1Tl + (size_t)l * HH * DD, z1, stats, nullptr, NN);
        ab_kernel<<<1, HH>>>(stats, g1 + l * HH, b1 + l * HH, HH, 1.0f / NN, ab);

        cudaMemsetAsync(stats, 0, 2 * DD * sizeof(float));
        gemm_mma<1, DD, HH><<<dim3(GB, 1), 256, GEMM_SMEM>>>(
            z1, W2Th + (size_t)l * DD * HH, W2Tl + (size_t)l * DD * HH, z2, stats, ab, NN);
        ab_kernel<<<1, DD>>>(stats, g2 + l * DD, b2 + l * DD, DD, 1.0f / NN, ab);

        bnrelu_pool<<<(NN * DD / 4 + 255) / 256, 256>>>(z2, ab, gid, h, agg, poolSlot, l * DD);
    }
}

extern "C" void kernel_launch(void* const* d_in, const int* in_sizes, int n_in,
                              void* d_out, int out_size) {
    const float* feat       = (const float*)d_in[0];
    const int*   src        = (const int*)d_in[1];
    const int*   dst        = (const int*)d_in[2];
    const int*   graph_ids  = (const int*)d_in[3];
    const int*   mask_nodes = (const int*)d_in[4];
    const float* mask_token = (const float*)d_in[5];
    const float* enc_W1 = (const float*)d_in[6];
    const float* enc_g1 = (const float*)d_in[7];
    const float* enc_b1 = (const float*)d_in[8];
    const float* enc_W2 = (const float*)d_in[9];
    const float* enc_g2 = (const float*)d_in[10];
    const float* enc_b2 = (const float*)d_in[11];
    const float* con_W1 = (const float*)d_in[12];
    const float* con_g1 = (const float*)d_in[13];
    const float* con_b1 = (const float*)d_in[14];
    const float* con_W2 = (const float*)d_in[15];
    const float* con_g2 = (const float*)d_in[16];
    const float* con_b2 = (const float*)d_in[17];
    const float* pW1 = (const float*)d_in[18];
    const float* pb1 = (const float*)d_in[19];
    const float* pW2 = (const float*)d_in[20];
    const float* pb2 = (const float*)d_in[21];
    int nMask = in_sizes[4];

    float *x, *h, *agg, *z1, *z2, *pool, *stats, *ab, *p2, *norms;
    float *w1h, *w1l, *w2h, *w2l;
    cudaGetSymbolAddress((void**)&x, g_x);
    cudaGetSymbolAddress((void**)&h, g_h);
    cudaGetSymbolAddress((void**)&agg, g_agg);
    cudaGetSymbolAddress((void**)&z1, g_z1);
    cudaGetSymbolAddress((void**)&z2, g_z2);
    cudaGetSymbolAddress((void**)&pool, g_pool);
    cudaGetSymbolAddress((void**)&stats, g_stats);
    cudaGetSymbolAddress((void**)&ab, g_ab);
    cudaGetSymbolAddress((void**)&p2, g_p2);
    cudaGetSymbolAddress((void**)&norms, g_norms);
    cudaGetSymbolAddress((void**)&w1h, g_W1T_hi);
    cudaGetSymbolAddress((void**)&w1l, g_W1T_lo);
    cudaGetSymbolAddress((void**)&w2h, g_W2T_hi);
    cudaGetSymbolAddress((void**)&w2l, g_W2T_lo);

    cudaFuncSetAttribute(gemm_mma<0, HH, DD>, cudaFuncAttributeMaxDynamicSharedMemorySize, GEMM_SMEM);
    cudaFuncSetAttribute(gemm_mma<1, DD, HH>, cudaFuncAttributeMaxDynamicSharedMemorySize, GEMM_SMEM);

    const int T1 = LL * DD * HH;
    tsplit<<<(T1 + 255) / 256, 256>>>(enc_W1, w1h, w1l, DD, HH, T1);
    tsplit<<<(T1 + 255) / 256, 256>>>(con_W1, w1h + T1, w1l + T1, DD, HH, T1);
    tsplit<<<(T1 + 255) / 256, 256>>>(enc_W2, w2h, w2l, HH, DD, T1);
    tsplit<<<(T1 + 255) / 256, 256>>>(con_W2, w2h + T1, w2l + T1, HH, DD, T1);

    cudaMemcpyAsync(x, feat, (size_t)NN * DD * sizeof(float), cudaMemcpyDeviceToDevice);
    mask_kernel<<<(nMask * DD + 255) / 256, 256>>>(x, mask_nodes, mask_token, nMask);

    cudaMemsetAsync(pool, 0, 2 * BB * LL * DD * sizeof(float));

    run_encoder(x, src, dst, graph_ids, w1h, w1l, w2h, w2l,
                enc_g1, enc_b1, enc_g2, enc_b2, agg, z1, z2, h, stats, ab, pool);
    run_encoder(feat, src, dst, graph_ids, w1h + T1, w1l + T1, w2h + T1, w2l + T1,
                con_g1, con_b1, con_g2, con_b2, agg, z1, z2, h, stats, ab,
                pool + BB * LL * DD);

    proj_kernel<<<BB, 192>>>(pool, pW1, pb1, pW2, pb2, p2);
    proj_kernel<<<BB, 192>>>(pool + BB * LL * DD, pW1, pb1, pW2, pb2, p2 + BB * 128);

    norms_kernel<<<2 * BB, 128>>>(p2, norms);

    cudaMemsetAsync(d_out, 0, sizeof(float));
    loss_kernel<<<BB, 256>>>(p2 + BB * 128, p2, norms + BB, norms, (float*)d_out);
}

// round 6
// speedup vs baseline: 2.4815x; 1.3921x over previous
#include <cuda_runtime.h>
#include <cuda_bf16.h>
#include <math.h>
#include <stdint.h>

#define NN 50000
#define EE 800000
#define BB 256
#define DD 128
#define HH 256
#define LL 3
#define TEMP 0.2f
#define BN_EPS 1e-5f

// ---------------- scratch (device globals) ----------------
__device__ __align__(16) float g_x[(size_t)NN * DD];
__device__ __align__(16) float g_h[(size_t)NN * DD];
__device__ __align__(16) float g_agg[(size_t)NN * DD];
__device__ __align__(16) float g_z1[(size_t)NN * HH];
__device__ __align__(16) float g_z2[(size_t)NN * DD];
__device__ __align__(16) float g_pool[2 * BB * LL * DD];
__device__ __align__(16) float g_stats[2 * HH];
__device__ __align__(16) float g_ab[2 * HH];
__device__ __align__(16) float g_p2[2 * BB * 128];
__device__ float g_norms[2 * BB];
// weights transposed + split: W1T [enc][L][HH][DD], W2T [enc][L][DD][HH]
__device__ __align__(16) float g_W1T_hi[2 * LL * HH * DD];
__device__ __align__(16) float g_W1T_lo[2 * LL * HH * DD];
__device__ __align__(16) float g_W2T_hi[2 * LL * DD * HH];
__device__ __align__(16) float g_W2T_lo[2 * LL * DD * HH];
// CSR
__device__ int g_rowptr[NN + 1];
__device__ int g_cnt[NN];
__device__ int g_col[EE];

// ---------------- helpers ----------------
__device__ __forceinline__ float tf32_round(float x) {
    uint32_t u;
    asm("cvt.rna.tf32.f32 %0, %1;" : "=r"(u) : "f"(x));
    return __uint_as_float(u);
}
__device__ __forceinline__ void red_add_v4(float* p, float4 v) {
    asm volatile("red.global.add.v4.f32 [%0], {%1,%2,%3,%4};"
                 :: "l"(p), "f"(v.x), "f"(v.y), "f"(v.z), "f"(v.w) : "memory");
}
__device__ __forceinline__ void mma_tf32(float* c, const uint32_t* a, const uint32_t* b) {
    asm volatile(
        "mma.sync.aligned.m16n8k8.row.col.f32.tf32.tf32.f32 "
        "{%0,%1,%2,%3}, {%4,%5,%6,%7}, {%8,%9}, {%0,%1,%2,%3};"
        : "+f"(c[0]), "+f"(c[1]), "+f"(c[2]), "+f"(c[3])
        : "r"(a[0]), "r"(a[1]), "r"(a[2]), "r"(a[3]), "r"(b[0]), "r"(b[1]));
}

// ---------------- CSR build ----------------
__global__ void count_kernel(const int* __restrict__ dst, int* __restrict__ cnt) {
    int e = blockIdx.x * blockDim.x + threadIdx.x;
    if (e < EE) atomicAdd(&cnt[dst[e]], 1);
}

__global__ void scan_kernel(const int* __restrict__ cnt, int* __restrict__ rowptr) {
    __shared__ int wsums[32];
    __shared__ int s_carry;
    int t = threadIdx.x, lane = t & 31, w = t >> 5;
    if (t == 0) s_carry = 0;
    __syncthreads();
    for (int base = 0; base < NN; base += 1024) {
        int i = base + t;
        int v = (i < NN) ? cnt[i] : 0;
        int x = v;
#pragma unroll
        for (int o = 1; o < 32; o <<= 1) {
            int y = __shfl_up_sync(0xffffffff, x, o);
            if (lane >= o) x += y;
        }
        if (lane == 31) wsums[w] = x;
        __syncthreads();
        if (w == 0) {
            int s = wsums[lane];
#pragma unroll
            for (int o = 1; o < 32; o <<= 1) {
                int y = __shfl_up_sync(0xffffffff, s, o);
                if (lane >= o) s += y;
            }
            wsums[lane] = s;
        }
        __syncthreads();
        int excl = x - v + (w ? wsums[w - 1] : 0) + s_carry;
        if (i < NN) rowptr[i] = excl;
        __syncthreads();
        if (t == 1023) s_carry += x + wsums[30];
        __syncthreads();
    }
    if (t == 0) rowptr[NN] = s_carry;
}

__global__ void fill_kernel(const int* __restrict__ src, const int* __restrict__ dst,
                            const int* __restrict__ rowptr, int* __restrict__ cnt,
                            int* __restrict__ col) {
    int e = blockIdx.x * blockDim.x + threadIdx.x;
    if (e >= EE) return;
    int d = dst[e];
    int pos = __ldg(rowptr + d) + atomicAdd(&cnt[d], 1);
    col[pos] = src[e];
}

// ---------------- gather: agg[n] = h[n] + sum_{m in N(n)} h[m] ----------------
__global__ void gather_kernel(const float* __restrict__ hin, const int* __restrict__ rowptr,
                              const int* __restrict__ col, float* __restrict__ agg) {
    int wid = (blockIdx.x * blockDim.x + threadIdx.x) >> 5;
    if (wid >= NN) return;
    int lane = threadIdx.x & 31;
    int r0 = __ldg(rowptr + wid), r1 = __ldg(rowptr + wid + 1);
    float4 acc = *reinterpret_cast<const float4*>(hin + (size_t)wid * DD + lane * 4);
    for (int base = r0; base < r1; base += 32) {
        int idx = (base + lane < r1) ? __ldg(col + base + lane) : 0;
        int m = min(32, r1 - base);
        int j = 0;
        for (; j + 4 <= m; j += 4) {
            int n0 = __shfl_sync(0xffffffff, idx, j);
            int n1 = __shfl_sync(0xffffffff, idx, j + 1);
            int n2 = __shfl_sync(0xffffffff, idx, j + 2);
            int n3 = __shfl_sync(0xffffffff, idx, j + 3);
            float4 v0 = *reinterpret_cast<const float4*>(hin + (size_t)n0 * DD + lane * 4);
            float4 v1 = *reinterpret_cast<const float4*>(hin + (size_t)n1 * DD + lane * 4);
            float4 v2 = *reinterpret_cast<const float4*>(hin + (size_t)n2 * DD + lane * 4);
            float4 v3 = *reinterpret_cast<const float4*>(hin + (size_t)n3 * DD + lane * 4);
            acc.x += v0.x + v1.x + v2.x + v3.x;
            acc.y += v0.y + v1.y + v2.y + v3.y;
            acc.z += v0.z + v1.z + v2.z + v3.z;
            acc.w += v0.w + v1.w + v2.w + v3.w;
        }
        for (; j < m; j++) {
            int n = __shfl_sync(0xffffffff, idx, j);
            float4 v = *reinterpret_cast<const float4*>(hin + (size_t)n * DD + lane * 4);
            acc.x += v.x; acc.y += v.y; acc.z += v.z; acc.w += v.w;
        }
    }
    *reinterpret_cast<float4*>(agg + (size_t)wid * DD + lane * 4) = acc;
}

// ---------------- small kernels ----------------
__global__ void mask_kernel(float* __restrict__ x, const int* __restrict__ idx,
                            const float* __restrict__ tok, int nMask) {
    int i = blockIdx.x * blockDim.x + threadIdx.x;
    if (i >= nMask * DD) return;
    int m = i >> 7, c = i & 127;
    x[(size_t)idx[m] * DD + c] = tok[c];
}

__global__ void ab_kernel(const float* __restrict__ stats, const float* __restrict__ g,
                          const float* __restrict__ b, int C, float invM, float* __restrict__ ab) {
    int t = threadIdx.x;
    if (t < C) {
        float m = stats[t] * invM;
        float var = stats[C + t] * invM - m * m;
        float a = g[t] * rsqrtf(var + BN_EPS);
        ab[t] = a;
        ab[C + t] = b[t] - m * a;
    }
}

__global__ void bnrelu_pool(const float* __restrict__ Z, const float* __restrict__ ab,
                            const int* __restrict__ gid, float* __restrict__ h,
                            float* __restrict__ pool, int colOff) {
    int idx = blockIdx.x * blockDim.x + threadIdx.x;
    if (idx >= NN * DD / 4) return;
    int r = idx >> 5;
    int c = (idx & 31) * 4;
    float4 z = *reinterpret_cast<const float4*>(Z + (size_t)idx * 4);
    float4 sa = *reinterpret_cast<const float4*>(ab + c);
    float4 sc = *reinterpret_cast<const float4*>(ab + DD + c);
    float4 v;
    v.x = fmaxf(fmaf(z.x, sa.x, sc.x), 0.f);
    v.y = fmaxf(fmaf(z.y, sa.y, sc.y), 0.f);
    v.z = fmaxf(fmaf(z.z, sa.z, sc.z), 0.f);
    v.w = fmaxf(fmaf(z.w, sa.w, sc.w), 0.f);
    *reinterpret_cast<float4*>(h + (size_t)idx * 4) = v;
    red_add_v4(&pool[(size_t)gid[r] * (LL * DD) + colOff + c], v);
}

__global__ void proj_kernel(const float* __restrict__ pool, const float* __restrict__ pW1,
                            const float* __restrict__ pb1, const float* __restrict__ pW2,
                            const float* __restrict__ pb2, float* __restrict__ out) {
    __shared__ float row[LL * DD];
    __shared__ float h1[192];
    int i = blockIdx.x;
    int t = threadIdx.x;
    for (int k = t; k < LL * DD; k += 192) row[k] = pool[(size_t)i * (LL * DD) + k];
    __syncthreads();
    float s = pb1[t];
    for (int k = 0; k < LL * DD; k++) s += row[k] * pW1[(size_t)k * 192 + t];
    h1[t] = fmaxf(s, 0.f);
    __syncthreads();
    if (t < 128) {
        float s2 = pb2[t];
        for (int k = 0; k < 192; k++) s2 += h1[k] * pW2[(size_t)k * 128 + t];
        out[(size_t)i * 128 + t] = s2;
    }
}

__global__ void norms_kernel(const float* __restrict__ p, float* __restrict__ nrm) {
    int row = blockIdx.x, t = threadIdx.x;
    float v = p[(size_t)row * 128 + t];
    v *= v;
    for (int o = 16; o; o >>= 1) v += __shfl_down_sync(0xffffffff, v, o);
    __shared__ float ws[4];
    if ((t & 31) == 0) ws[t >> 5] = v;
    __syncthreads();
    if (t == 0) nrm[row] = sqrtf(ws[0] + ws[1] + ws[2] + ws[3]);
}

__global__ void loss_kernel(const float* __restrict__ ch, const float* __restrict__ cm,
                            const float* __restrict__ n_ch, const float* __restrict__ n_cm,
                            float* __restrict__ out) {
    int i = blockIdx.x;
    int t = threadIdx.x;
    __shared__ float sh[128];
    __shared__ float red[256];
    __shared__ float posv;
    if (t < 128) sh[t] = ch[(size_t)i * 128 + t];
    __syncthreads();
    float d = 0.f;
    const float* rowj = cm + (size_t)t * 128;
    for (int k = 0; k < 128; k++) d += sh[k] * rowj[k];
    float s = expf(d / (n_ch[i] * n_cm[t]) * (1.0f / TEMP));
    if (t == i) posv = s;
    red[t] = s;
    __syncthreads();
    for (int o = 128; o; o >>= 1) {
        if (t < o) red[t] += red[t + o];
        __syncthreads();
    }
    if (t == 0) {
        float sum = red[0];
        float li = -logf(posv / (sum - posv));
        atomicAdd(out, li * (1.0f / BB));
    }
}

// weight prep: [L, K, N] -> transposed hi/lo [L, N, K]
__global__ void tsplit(const float* __restrict__ W, float* __restrict__ hi,
                       float* __restrict__ lo, int K, int N, int total) {
    int i = blockIdx.x * blockDim.x + threadIdx.x;
    if (i >= total) return;
    int l = i / (K * N), rem = i % (K * N);
    int k = rem / N, n = rem % N;
    float v = W[i];
    float h = tf32_round(v);
    size_t o = (size_t)l * K * N + (size_t)n * K + k;
    hi[o] = h;
    lo[o] = v - h;
}

// ---------------- 2xTF32 mma.sync GEMM, fused BN-stats epilogue ----------------
// C[M, NT] = rna(f(A))[M, KT] @ (Bh + Bl)^T ; B stored [NT, KT] pre-split.
// MODE 0: f(A)=A.  MODE 1: f(A)=relu(A*ab[k]+ab[KT+k]).
// CTA tile 128x128, 8 warps (2x4), warp tile 64x32, occupancy 2.

#define PAD 36
#define GEMM_SMEM (3 * 128 * PAD * 4)   // 55296 B

template <int MODE, int NT, int KT>
__global__ __launch_bounds__(256, 2)
void gemm_mma(const float* __restrict__ A, const float* __restrict__ Bh,
              const float* __restrict__ Bl, float* __restrict__ C,
              float* __restrict__ stats, const float* __restrict__ ab, int M) {
    extern __shared__ float sm[];
    float* As  = sm;                       // [128][PAD]
    float* Bhs = As + 128 * PAD;
    float* Bls = Bhs + 128 * PAD;
    __shared__ float ssum[128], ssq[128];

    const int tid = threadIdx.x;
    const int lane = tid & 31, w = tid >> 5;
    const int mw = w >> 2, nw = w & 3;
    const int bm = blockIdx.x * 128, bn = blockIdx.y * 128;

    float acc[4][4][4];
#pragma unroll
    for (int mi = 0; mi < 4; mi++)
#pragma unroll
        for (int ni = 0; ni < 4; ni++)
#pragma unroll
            for (int r = 0; r < 4; r++) acc[mi][ni][r] = 0.f;

    const int lrow = tid >> 1;
    const int lcol0 = (tid & 1) * 16;
    const bool rok = (bm + lrow) < M;
    const float* Arow = A + (size_t)(bm + lrow) * KT;
    const float* Bhrow = Bh + (size_t)(bn + lrow) * KT;
    const float* Blrow = Bl + (size_t)(bn + lrow) * KT;

    const int frow = lane >> 2;
    const int fcol = lane & 3;

    for (int k0 = 0; k0 < KT; k0 += 32) {
        // ---- stage A (rna-rounded) ----
#pragma unroll
        for (int i = 0; i < 4; i++) {
            int col = lcol0 + i * 4;
            float4 v = make_float4(0.f, 0.f, 0.f, 0.f);
            if (rok) {
                v = *reinterpret_cast<const float4*>(Arow + k0 + col);
                if (MODE == 1) {
                    float4 sa = *reinterpret_cast<const float4*>(ab + k0 + col);
                    float4 sc = *reinterpret_cast<const float4*>(ab + KT + k0 + col);
                    v.x = fmaxf(fmaf(v.x, sa.x, sc.x), 0.f);
                    v.y = fmaxf(fmaf(v.y, sa.y, sc.y), 0.f);
                    v.z = fmaxf(fmaf(v.z, sa.z, sc.z), 0.f);
                    v.w = fmaxf(fmaf(v.w, sa.w, sc.w), 0.f);
                }
            }
            float4 hi = make_float4(tf32_round(v.x), tf32_round(v.y),
                                    tf32_round(v.z), tf32_round(v.w));
            *reinterpret_cast<float4*>(As + lrow * PAD + col) = hi;
        }
        // ---- stage B ----
#pragma unroll
        for (int i = 0; i < 4; i++) {
            int col = lcol0 + i * 4;
            float4 vh = *reinterpret_cast<const float4*>(Bhrow + k0 + col);
            float4 vl = *reinterpret_cast<const float4*>(Blrow + k0 + col);
            *reinterpret_cast<float4*>(Bhs + lrow * PAD + col) = vh;
            *reinterpret_cast<float4*>(Bls + lrow * PAD + col) = vl;
        }
        __syncthreads();

#pragma unroll
        for (int kk = 0; kk < 4; kk++) {
            const int k = kk * 8;
            uint32_t af[4][4];
#pragma unroll
            for (int mi = 0; mi < 4; mi++) {
                int r0 = mw * 64 + mi * 16 + frow;
                int c0 = k + fcol;
                af[mi][0] = __float_as_uint(As[r0 * PAD + c0]);
                af[mi][1] = __float_as_uint(As[(r0 + 8) * PAD + c0]);
                af[mi][2] = __float_as_uint(As[r0 * PAD + c0 + 4]);
                af[mi][3] = __float_as_uint(As[(r0 + 8) * PAD + c0 + 4]);
            }
            uint32_t bfh[4][2], bfl[4][2];
#pragma unroll
            for (int ni = 0; ni < 4; ni++) {
                int n0 = nw * 32 + ni * 8 + frow;
                int kb = k + fcol;
                bfh[ni][0] = __float_as_uint(Bhs[n0 * PAD + kb]);
                bfh[ni][1] = __float_as_uint(Bhs[n0 * PAD + kb + 4]);
                bfl[ni][0] = __float_as_uint(Bls[n0 * PAD + kb]);
                bfl[ni][1] = __float_as_uint(Bls[n0 * PAD + kb + 4]);
            }
#pragma unroll
            for (int mi = 0; mi < 4; mi++)
#pragma unroll
                for (int ni = 0; ni < 4; ni++) {
                    mma_tf32(acc[mi][ni], af[mi], bfh[ni]);
                    mma_tf32(acc[mi][ni], af[mi], bfl[ni]);
                }
        }
        __syncthreads();
    }

    // ---- epilogue: C store + fused column stats ----
    if (tid < 128) { ssum[tid] = 0.f; ssq[tid] = 0.f; }
    __syncthreads();

#pragma unroll
    for (int mi = 0; mi < 4; mi++) {
#pragma unroll
        for (int ni = 0; ni < 4; ni++) {
            int row = bm + mw * 64 + mi * 16 + frow;
            int coll = nw * 32 + ni * 8 + 2 * fcol;
            float* a = acc[mi][ni];
            if (row < M)
                *reinterpret_cast<float2*>(C + (size_t)row * NT + bn + coll) =
                    make_float2(a[0], a[1]);
            if (row + 8 < M)
                *reinterpret_cast<float2*>(C + (size_t)(row + 8) * NT + bn + coll) =
                    make_float2(a[2], a[3]);
        }
    }

#pragma unroll
    for (int ni = 0; ni < 4; ni++) {
        float s0 = 0.f, s1 = 0.f, q0 = 0.f, q1 = 0.f;
#pragma unroll
        for (int mi = 0; mi < 4; mi++) {
            float* a = acc[mi][ni];
            s0 += a[0] + a[2];
            s1 += a[1] + a[3];
            q0 += a[0] * a[0] + a[2] * a[2];
            q1 += a[1] * a[1] + a[3] * a[3];
        }
#pragma unroll
        for (int off = 4; off < 32; off <<= 1) {
            s0 += __shfl_xor_sync(0xffffffff, s0, off);
            s1 += __shfl_xor_sync(0xffffffff, s1, off);
            q0 += __shfl_xor_sync(0xffffffff, q0, off);
            q1 += __shfl_xor_sync(0xffffffff, q1, off);
        }
        if (lane < 4) {
            int coll = nw * 32 + ni * 8 + 2 * fcol;
            atomicAdd(&ssum[coll], s0);
            atomicAdd(&ssum[coll + 1], s1);
            atomicAdd(&ssq[coll], q0);
            atomicAdd(&ssq[coll + 1], q1);
        }
    }
    __syncthreads();
    if (tid < 128) {
        atomicAdd(&stats[bn + tid], ssum[tid]);
        atomicAdd(&stats[NT + bn + tid], ssq[tid]);
    }
}

// ---------------- host orchestration ----------------

static void run_encoder(const float* input, const int* rowptr, const int* colidx,
                        const int* gid,
                        const float* W1Th, const float* W1Tl,
                        const float* W2Th, const float* W2Tl,
                        const float* g1, const float* b1,
                        const float* g2, const float* b2,
                        float* agg, float* z1, float* z2, float* h,
                        float* stats, float* ab, float* poolSlot) {
    const int GB = (NN + 127) / 128;   // 391
    for (int l = 0; l < LL; l++) {
        gather_kernel<<<(NN * 32 + 255) / 256, 256>>>(l == 0 ? input : h, rowptr, colidx, agg);

        cudaMemsetAsync(stats, 0, 2 * HH * sizeof(float));
        gemm_mma<0, HH, DD><<<dim3(GB, HH / 128), 256, GEMM_SMEM>>>(
            agg, W1Th + (size_t)l * HH * DD, W1Tl + (size_t)l * HH * DD, z1, stats, nullptr, NN);
        ab_kernel<<<1, HH>>>(stats, g1 + l * HH, b1 + l * HH, HH, 1.0f / NN, ab);

        cudaMemsetAsync(stats, 0, 2 * DD * sizeof(float));
        gemm_mma<1, DD, HH><<<dim3(GB, 1), 256, GEMM_SMEM>>>(
            z1, W2Th + (size_t)l * DD * HH, W2Tl + (size_t)l * DD * HH, z2, stats, ab, NN);
        ab_kernel<<<1, DD>>>(stats, g2 + l * DD, b2 + l * DD, DD, 1.0f / NN, ab);

        bnrelu_pool<<<(NN * DD / 4 + 255) / 256, 256>>>(z2, ab, gid, h, poolSlot, l * DD);
    }
}

extern "C" void kernel_launch(void* const* d_in, const int* in_sizes, int n_in,
                              void* d_out, int out_size) {
    const float* feat       = (const float*)d_in[0];
    const int*   src        = (const int*)d_in[1];
    const int*   dst        = (const int*)d_in[2];
    const int*   graph_ids  = (const int*)d_in[3];
    const int*   mask_nodes = (const int*)d_in[4];
    const float* mask_token = (const float*)d_in[5];
    const float* enc_W1 = (const float*)d_in[6];
    const float* enc_g1 = (const float*)d_in[7];
    const float* enc_b1 = (const float*)d_in[8];
    const float* enc_W2 = (const float*)d_in[9];
    const float* enc_g2 = (const float*)d_in[10];
    const float* enc_b2 = (const float*)d_in[11];
    const float* con_W1 = (const float*)d_in[12];
    const float* con_g1 = (const float*)d_in[13];
    const float* con_b1 = (const float*)d_in[14];
    const float* con_W2 = (const float*)d_in[15];
    const float* con_g2 = (const float*)d_in[16];
    const float* con_b2 = (const float*)d_in[17];
    const float* pW1 = (const float*)d_in[18];
    const float* pb1 = (const float*)d_in[19];
    const float* pW2 = (const float*)d_in[20];
    const float* pb2 = (const float*)d_in[21];
    int nMask = in_sizes[4];

    float *x, *h, *agg, *z1, *z2, *pool, *stats, *ab, *p2, *norms;
    float *w1h, *w1l, *w2h, *w2l;
    int *rowptr, *cnt, *colidx;
    cudaGetSymbolAddress((void**)&x, g_x);
    cudaGetSymbolAddress((void**)&h, g_h);
    cudaGetSymbolAddress((void**)&agg, g_agg);
    cudaGetSymbolAddress((void**)&z1, g_z1);
    cudaGetSymbolAddress((void**)&z2, g_z2);
    cudaGetSymbolAddress((void**)&pool, g_pool);
    cudaGetSymbolAddress((void**)&stats, g_stats);
    cudaGetSymbolAddress((void**)&ab, g_ab);
    cudaGetSymbolAddress((void**)&p2, g_p2);
    cudaGetSymbolAddress((void**)&norms, g_norms);
    cudaGetSymbolAddress((void**)&w1h, g_W1T_hi);
    cudaGetSymbolAddress((void**)&w1l, g_W1T_lo);
    cudaGetSymbolAddress((void**)&w2h, g_W2T_hi);
    cudaGetSymbolAddress((void**)&w2l, g_W2T_lo);
    cudaGetSymbolAddress((void**)&rowptr, g_rowptr);
    cudaGetSymbolAddress((void**)&cnt, g_cnt);
    cudaGetSymbolAddress((void**)&colidx, g_col);

    cudaFuncSetAttribute(gemm_mma<0, HH, DD>, cudaFuncAttributeMaxDynamicSharedMemorySize, GEMM_SMEM);
    cudaFuncSetAttribute(gemm_mma<1, DD, HH>, cudaFuncAttributeMaxDynamicSharedMemorySize, GEMM_SMEM);

    // ---- CSR build (once; reused by both encoders, all layers) ----
    cudaMemsetAsync(cnt, 0, NN * sizeof(int));
    count_kernel<<<(EE + 255) / 256, 256>>>(dst, cnt);
    scan_kernel<<<1, 1024>>>(cnt, rowptr);
    cudaMemsetAsync(cnt, 0, NN * sizeof(int));
    fill_kernel<<<(EE + 255) / 256, 256>>>(src, dst, rowptr, cnt, colidx);

    // ---- weight prep ----
    const int T1 = LL * DD * HH;
    tsplit<<<(T1 + 255) / 256, 256>>>(enc_W1, w1h, w1l, DD, HH, T1);
    tsplit<<<(T1 + 255) / 256, 256>>>(con_W1, w1h + T1, w1l + T1, DD, HH, T1);
    tsplit<<<(T1 + 255) / 256, 256>>>(enc_W2, w2h, w2l, HH, DD, T1);
    tsplit<<<(T1 + 255) / 256, 256>>>(con_W2, w2h + T1, w2l + T1, HH, DD, T1);

    cudaMemcpyAsync(x, feat, (size_t)NN * DD * sizeof(float), cudaMemcpyDeviceToDevice);
    mask_kernel<<<(nMask * DD + 255) / 256, 256>>>(x, mask_nodes, mask_token, nMask);

    cudaMemsetAsync(pool, 0, 2 * BB * LL * DD * sizeof(float));

    run_encoder(x, rowptr, colidx, graph_ids, w1h, w1l, w2h, w2l,
                enc_g1, enc_b1, enc_g2, enc_b2, agg, z1, z2, h, stats, ab, pool);
    run_encoder(feat, rowptr, colidx, graph_ids, w1h + T1, w1l + T1, w2h + T1, w2l + T1,
                con_g1, con_b1, con_g2, con_b2, agg, z1, z2, h, stats, ab,
                pool + BB * LL * DD);

    proj_kernel<<<BB, 192>>>(pool, pW1, pb1, pW2, pb2, p2);
    proj_kernel<<<BB, 192>>>(pool + BB * LL * DD, pW1, pb1, pW2, pb2, p2 + BB * 128);

    norms_kernel<<<2 * BB, 128>>>(p2, norms);

    cudaMemsetAsync(d_out, 0, sizeof(float));
    loss_kernel<<<BB, 256>>>(p2 + BB * 128, p2, norms + BB, norms, (float*)d_out);
}

// round 9
// speedup vs baseline: 2.9022x; 1.1695x over previous
#include <cuda_runtime.h>
#include <cuda_bf16.h>
#include <math.h>
#include <stdint.h>

#define NN 50000
#define EE 800000
#define BB 256
#define DD 128
#define HH 256
#define LL 3
#define TEMP 0.2f
#define BN_EPS 1e-5f

// ---------------- scratch (device globals) ----------------
__device__ __align__(16) float g_x[(size_t)NN * DD];
// per-encoder scratch, contiguous [2][...] so kernels index by encoder
__device__ __align__(16) float g_h[2][(size_t)NN * DD];
__device__ __align__(16) float g_agg[2][(size_t)NN * DD];
__device__ __align__(16) float g_z1[2][(size_t)NN * HH];
__device__ __align__(16) float g_z2[2][(size_t)NN * DD];
__device__ __align__(16) float g_statsArena[2 * LL * 2 * 512];   // [enc][L][st1/st2][512]
__device__ __align__(16) float g_pool[2 * BB * LL * DD];
__device__ __align__(16) float g_p2[2 * BB * 128];
__device__ float g_norms[2 * BB];
// weights transposed + split: [enc][L][HH][DD] / [enc][L][DD][HH]
__device__ __align__(16) float g_W1T_hi[2 * LL * HH * DD];
__device__ __align__(16) float g_W1T_lo[2 * LL * HH * DD];
__device__ __align__(16) float g_W2T_hi[2 * LL * DD * HH];
__device__ __align__(16) float g_W2T_lo[2 * LL * DD * HH];
// CSR
__device__ int g_rowptr[NN + 1];
__device__ int g_cnt[NN];
__device__ int g_col[EE];

#define ENC_W (LL * DD * HH)          // per-encoder weight stride
#define ENC_ST (LL * 1024)            // per-encoder stats stride

// ---------------- helpers ----------------
__device__ __forceinline__ float tf32_round(float x) {
    uint32_t u;
    asm("cvt.rna.tf32.f32 %0, %1;" : "=r"(u) : "f"(x));
    return __uint_as_float(u);
}
__device__ __forceinline__ void red_add_v4(float* p, float4 v) {
    asm volatile("red.global.add.v4.f32 [%0], {%1,%2,%3,%4};"
                 :: "l"(p), "f"(v.x), "f"(v.y), "f"(v.z), "f"(v.w) : "memory");
}
__device__ __forceinline__ void mma_tf32(float* c, const uint32_t* a, const uint32_t* b) {
    asm volatile(
        "mma.sync.aligned.m16n8k8.row.col.f32.tf32.tf32.f32 "
        "{%0,%1,%2,%3}, {%4,%5,%6,%7}, {%8,%9}, {%0,%1,%2,%3};"
        : "+f"(c[0]), "+f"(c[1]), "+f"(c[2]), "+f"(c[3])
        : "r"(a[0]), "r"(a[1]), "r"(a[2]), "r"(a[3]), "r"(b[0]), "r"(b[1]));
}

// ---------------- CSR build ----------------
__global__ void count_kernel(const int* __restrict__ dst, int* __restrict__ cnt) {
    int e = blockIdx.x * blockDim.x + threadIdx.x;
    if (e < EE) atomicAdd(&cnt[dst[e]], 1);
}

__global__ void scan_kernel(const int* __restrict__ cnt, int* __restrict__ rowptr) {
    __shared__ int wsums[32];
    __shared__ int s_carry;
    int t = threadIdx.x, lane = t & 31, w = t >> 5;
    if (t == 0) s_carry = 0;
    __syncthreads();
    for (int base = 0; base < NN; base += 1024) {
        int i = base + t;
        int v = (i < NN) ? cnt[i] : 0;
        int x = v;
#pragma unroll
        for (int o = 1; o < 32; o <<= 1) {
            int y = __shfl_up_sync(0xffffffff, x, o);
            if (lane >= o) x += y;
        }
        if (lane == 31) wsums[w] = x;
        __syncthreads();
        if (w == 0) {
            int s = wsums[lane];
#pragma unroll
            for (int o = 1; o < 32; o <<= 1) {
                int y = __shfl_up_sync(0xffffffff, s, o);
                if (lane >= o) s += y;
            }
            wsums[lane] = s;
        }
        __syncthreads();
        int excl = x - v + (w ? wsums[w - 1] : 0) + s_carry;
        if (i < NN) rowptr[i] = excl;
        __syncthreads();
        if (t == 1023) s_carry += x + wsums[30];
        __syncthreads();
    }
    if (t == 0) rowptr[NN] = s_carry;
}

__global__ void fill_kernel(const int* __restrict__ src, const int* __restrict__ dst,
                            const int* __restrict__ rowptr, int* __restrict__ cnt,
                            int* __restrict__ col) {
    int e = blockIdx.x * blockDim.x + threadIdx.x;
    if (e >= EE) return;
    int d = dst[e];
    int pos = __ldg(rowptr + d) + atomicAdd(&cnt[d], 1);
    col[pos] = src[e];
}

// ---------- gather (both encoders): agg[n] = h[n] + sum_{m in N(n)} h[m] ------
__global__ void gather_kernel(const float* __restrict__ hin0, const float* __restrict__ hin1,
                              const int* __restrict__ rowptr, const int* __restrict__ col,
                              float* __restrict__ agg) {
    int enc = blockIdx.y;
    const float* hin = enc ? hin1 : hin0;
    agg += (size_t)enc * NN * DD;
    int wid = (blockIdx.x * blockDim.x + threadIdx.x) >> 5;
    if (wid >= NN) return;
    int lane = threadIdx.x & 31;
    int r0 = __ldg(rowptr + wid), r1 = __ldg(rowptr + wid + 1);
    float4 acc = *reinterpret_cast<const float4*>(hin + (size_t)wid * DD + lane * 4);
    for (int base = r0; base < r1; base += 32) {
        int idx = (base + lane < r1) ? __ldg(col + base + lane) : 0;
        int m = min(32, r1 - base);
        int j = 0;
        for (; j + 4 <= m; j += 4) {
            int n0 = __shfl_sync(0xffffffff, idx, j);
            int n1 = __shfl_sync(0xffffffff, idx, j + 1);
            int n2 = __shfl_sync(0xffffffff, idx, j + 2);
            int n3 = __shfl_sync(0xffffffff, idx, j + 3);
            float4 v0 = *reinterpret_cast<const float4*>(hin + (size_t)n0 * DD + lane * 4);
            float4 v1 = *reinterpret_cast<const float4*>(hin + (size_t)n1 * DD + lane * 4);
            float4 v2 = *reinterpret_cast<const float4*>(hin + (size_t)n2 * DD + lane * 4);
            float4 v3 = *reinterpret_cast<const float4*>(hin + (size_t)n3 * DD + lane * 4);
            acc.x += v0.x + v1.x + v2.x + v3.x;
            acc.y += v0.y + v1.y + v2.y + v3.y;
            acc.z += v0.z + v1.z + v2.z + v3.z;
            acc.w += v0.w + v1.w + v2.w + v3.w;
        }
        for (; j < m; j++) {
            int n = __shfl_sync(0xffffffff, idx, j);
            float4 v = *reinterpret_cast<const float4*>(hin + (size_t)n * DD + lane * 4);
            acc.x += v.x; acc.y += v.y; acc.z += v.z; acc.w += v.w;
        }
    }
    *reinterpret_cast<float4*>(agg + (size_t)wid * DD + lane * 4) = acc;
}

// ---------------- small kernels ----------------
__global__ void mask_kernel(float* __restrict__ x, const int* __restrict__ idx,
                            const float* __restrict__ tok, int nMask) {
    int i = blockIdx.x * blockDim.x + threadIdx.x;
    if (i >= nMask * DD) return;
    int m = i >> 7, c = i & 127;
    x[(size_t)idx[m] * DD + c] = tok[c];
}

// h = relu(bn(z2)) for BOTH encoders; ab from stats; pool scatter
__global__ void bnrelu_pool(const float* __restrict__ Z, const float* __restrict__ stats,
                            const float* __restrict__ g0, const float* __restrict__ g1,
                            const float* __restrict__ b0, const float* __restrict__ b1,
                            const int* __restrict__ gid, float* __restrict__ h,
                            float* __restrict__ pool, int colOff) {
    int enc = blockIdx.y;
    Z += (size_t)enc * NN * DD;
    h += (size_t)enc * NN * DD;
    stats += (size_t)enc * ENC_ST;
    pool += (size_t)enc * BB * LL * DD;
    const float* g = enc ? g1 : g0;
    const float* b = enc ? b1 : b0;

    __shared__ __align__(16) float sab[2 * DD];
    int t = threadIdx.x;
    if (t < DD) {
        float m = stats[t] * (1.0f / NN);
        float var = stats[DD + t] * (1.0f / NN) - m * m;
        float a = g[t] * rsqrtf(var + BN_EPS);
        sab[t] = a;
        sab[DD + t] = b[t] - m * a;
    }
    __syncthreads();
    int idx = blockIdx.x * blockDim.x + t;
    if (idx >= NN * DD / 4) return;
    int r = idx >> 5;
    int c = (idx & 31) * 4;
    float4 z = *reinterpret_cast<const float4*>(Z + (size_t)idx * 4);
    float4 sa = *reinterpret_cast<const float4*>(sab + c);
    float4 sc = *reinterpret_cast<const float4*>(sab + DD + c);
    float4 v;
    v.x = fmaxf(fmaf(z.x, sa.x, sc.x), 0.f);
    v.y = fmaxf(fmaf(z.y, sa.y, sc.y), 0.f);
    v.z = fmaxf(fmaf(z.z, sa.z, sc.z), 0.f);
    v.w = fmaxf(fmaf(z.w, sa.w, sc.w), 0.f);
    *reinterpret_cast<float4*>(h + (size_t)idx * 4) = v;
    red_add_v4(&pool[(size_t)gid[r] * (LL * DD) + colOff + c], v);
}

__global__ void proj_kernel(const float* __restrict__ pool, const float* __restrict__ pW1,
                            const float* __restrict__ pb1, const float* __restrict__ pW2,
                            const float* __restrict__ pb2, float* __restrict__ out) {
    __shared__ float row[LL * DD];
    __shared__ float h1[192];
    int i = blockIdx.x + blockIdx.y * BB;    // y: which pooled slot
    int t = threadIdx.x;
    for (int k = t; k < LL * DD; k += 192) row[k] = pool[(size_t)i * (LL * DD) + k];
    __syncthreads();
    float s = pb1[t];
    for (int k = 0; k < LL * DD; k++) s += row[k] * pW1[(size_t)k * 192 + t];
    h1[t] = fmaxf(s, 0.f);
    __syncthreads();
    if (t < 128) {
        float s2 = pb2[t];
        for (int k = 0; k < 192; k++) s2 += h1[k] * pW2[(size_t)k * 128 + t];
        out[(size_t)i * 128 + t] = s2;
    }
}

__global__ void norms_kernel(const float* __restrict__ p, float* __restrict__ nrm) {
    int row = blockIdx.x, t = threadIdx.x;
    float v = p[(size_t)row * 128 + t];
    v *= v;
    for (int o = 16; o; o >>= 1) v += __shfl_down_sync(0xffffffff, v, o);
    __shared__ float ws[4];
    if ((t & 31) == 0) ws[t >> 5] = v;
    __syncthreads();
    if (t == 0) nrm[row] = sqrtf(ws[0] + ws[1] + ws[2] + ws[3]);
}

__global__ void loss_kernel(const float* __restrict__ ch, const float* __restrict__ cm,
                            const float* __restrict__ n_ch, const float* __restrict__ n_cm,
                            float* __restrict__ out) {
    int i = blockIdx.x;
    int t = threadIdx.x;
    __shared__ float sh[128];
    __shared__ float red[256];
    __shared__ float posv;
    if (t < 128) sh[t] = ch[(size_t)i * 128 + t];
    __syncthreads();
    float d = 0.f;
    const float* rowj = cm + (size_t)t * 128;
    for (int k = 0; k < 128; k++) d += sh[k] * rowj[k];
    float s = expf(d / (n_ch[i] * n_cm[t]) * (1.0f / TEMP));
    if (t == i) posv = s;
    red[t] = s;
    __syncthreads();
    for (int o = 128; o; o >>= 1) {
        if (t < o) red[t] += red[t + o];
        __syncthreads();
    }
    if (t == 0) {
        float sum = red[0];
        float li = -logf(posv / (sum - posv));
        atomicAdd(out, li * (1.0f / BB));
    }
}

// weight prep: [L, K, N] -> transposed hi/lo [L, N, K]
__global__ void tsplit(const float* __restrict__ W, float* __restrict__ hi,
                       float* __restrict__ lo, int K, int N, int total) {
    int i = blockIdx.x * blockDim.x + threadIdx.x;
    if (i >= total) return;
    int l = i / (K * N), rem = i % (K * N);
    int k = rem / N, n = rem % N;
    float v = W[i];
    float h = tf32_round(v);
    size_t o = (size_t)l * K * N + (size_t)n * K + k;
    hi[o] = h;
    lo[o] = v - h;
}

// ---------------- 2xTF32 mma.sync GEMM (both encoders via blockIdx.z) ---------
// MODE 0: f(A)=A.  MODE 1: f(A)=relu(bn(A)) from stats_in.
// CTA tile 128x128, 8 warps (2x4), warp tile 64x32, occupancy 2.

#define PAD 36
#define GEMM_SMEM ((3 * 128 * PAD + 2 * 256) * 4)   // 57344 B

template <int MODE, int NT, int KT>
__global__ __launch_bounds__(256, 2)
void gemm_mma(const float* __restrict__ A, const float* __restrict__ Bh,
              const float* __restrict__ Bl, float* __restrict__ C,
              float* __restrict__ stats_out, const float* __restrict__ stats_in,
              const float* __restrict__ g0, const float* __restrict__ g1,
              const float* __restrict__ b0, const float* __restrict__ b1, int M) {
    const int enc = blockIdx.z;
    A += (size_t)enc * NN * KT;
    Bh += (size_t)enc * ENC_W;
    Bl += (size_t)enc * ENC_W;
    C += (size_t)enc * NN * NT;
    stats_out += (size_t)enc * ENC_ST;
    const float* g = enc ? g1 : g0;
    const float* b = enc ? b1 : b0;

    extern __shared__ float sm[];
    float* As  = sm;                       // [128][PAD]
    float* Bhs = As + 128 * PAD;
    float* Bls = Bhs + 128 * PAD;
    float* sab = Bls + 128 * PAD;          // [2*KT]
    __shared__ float ssum[128], ssq[128];

    const int tid = threadIdx.x;
    const int lane = tid & 31, w = tid >> 5;
    const int mw = w >> 2, nw = w & 3;
    const int bm = blockIdx.x * 128, bn = blockIdx.y * 128;

    if (MODE == 1) {
        const float* si = stats_in + (size_t)enc * ENC_ST;
        for (int i = tid; i < KT; i += 256) {
            float m = si[i] * (1.0f / NN);
            float var = si[KT + i] * (1.0f / NN) - m * m;
            float a = g[i] * rsqrtf(var + BN_EPS);
            sab[i] = a;
            sab[KT + i] = b[i] - m * a;
        }
        __syncthreads();
    }

    float acc[4][4][4];
#pragma unroll
    for (int mi = 0; mi < 4; mi++)
#pragma unroll
        for (int ni = 0; ni < 4; ni++)
#pragma unroll
            for (int r = 0; r < 4; r++) acc[mi][ni][r] = 0.f;

    const int lrow = tid >> 1;
    const int lcol0 = (tid & 1) * 16;
    const bool rok = (bm + lrow) < M;
    const float* Arow = A + (size_t)(bm + lrow) * KT;
    const float* Bhrow = Bh + (size_t)(bn + lrow) * KT;
    const float* Blrow = Bl + (size_t)(bn + lrow) * KT;

    const int frow = lane >> 2;
    const int fcol = lane & 3;

    for (int k0 = 0; k0 < KT; k0 += 32) {
        // ---- stage A (BN+ReLU fused, rna-rounded) ----
#pragma unroll
        for (int i = 0; i < 4; i++) {
            int col = lcol0 + i * 4;
            float4 v = make_float4(0.f, 0.f, 0.f, 0.f);
            if (rok) {
                v = *reinterpret_cast<const float4*>(Arow + k0 + col);
                if (MODE == 1) {
                    float4 sa = *reinterpret_cast<const float4*>(sab + k0 + col);
                    float4 sc = *reinterpret_cast<const float4*>(sab + KT + k0 + col);
                    v.x = fmaxf(fmaf(v.x, sa.x, sc.x), 0.f);
                    v.y = fmaxf(fmaf(v.y, sa.y, sc.y), 0.f);
                    v.z = fmaxf(fmaf(v.z, sa.z, sc.z), 0.f);
                    v.w = fmaxf(fmaf(v.w, sa.w, sc.w), 0.f);
                }
            }
            float4 hi = make_float4(tf32_round(v.x), tf32_round(v.y),
                                    tf32_round(v.z), tf32_round(v.w));
            *reinterpret_cast<float4*>(As + lrow * PAD + col) = hi;
        }
        // ---- stage B ----
#pragma unroll
        for (int i = 0; i < 4; i++) {
            int col = lcol0 + i * 4;
            float4 vh = *reinterpret_cast<const float4*>(Bhrow + k0 + col);
            float4 vl = *reinterpret_cast<const float4*>(Blrow + k0 + col);
            *reinterpret_cast<float4*>(Bhs + lrow * PAD + col) = vh;
            *reinterpret_cast<float4*>(Bls + lrow * PAD + col) = vl;
        }
        __syncthreads();

#pragma unroll
        for (int kk = 0; kk < 4; kk++) {
            const int k = kk * 8;
            uint32_t af[4][4];
#pragma unroll
            for (int mi = 0; mi < 4; mi++) {
                int r0 = mw * 64 + mi * 16 + frow;
                int c0 = k + fcol;
                af[mi][0] = __float_as_uint(As[r0 * PAD + c0]);
                af[mi][1] = __float_as_uint(As[(r0 + 8) * PAD + c0]);
                af[mi][2] = __float_as_uint(As[r0 * PAD + c0 + 4]);
                af[mi][3] = __float_as_uint(As[(r0 + 8) * PAD + c0 + 4]);
            }
            uint32_t bfh[4][2], bfl[4][2];
#pragma unroll
            for (int ni = 0; ni < 4; ni++) {
                int n0 = nw * 32 + ni * 8 + frow;
                int kb = k + fcol;
                bfh[ni][0] = __float_as_uint(Bhs[n0 * PAD + kb]);
                bfh[ni][1] = __float_as_uint(Bhs[n0 * PAD + kb + 4]);
                bfl[ni][0] = __float_as_uint(Bls[n0 * PAD + kb]);
                bfl[ni][1] = __float_as_uint(Bls[n0 * PAD + kb + 4]);
            }
#pragma unroll
            for (int mi = 0; mi < 4; mi++)
#pragma unroll
                for (int ni = 0; ni < 4; ni++) {
                    mma_tf32(acc[mi][ni], af[mi], bfh[ni]);
                    mma_tf32(acc[mi][ni], af[mi], bfl[ni]);
                }
        }
        __syncthreads();
    }

    // ---- epilogue: C store + fused column stats ----
    if (tid < 128) { ssum[tid] = 0.f; ssq[tid] = 0.f; }
    __syncthreads();

#pragma unroll
    for (int mi = 0; mi < 4; mi++) {
#pragma unroll
        for (int ni = 0; ni < 4; ni++) {
            int row = bm + mw * 64 + mi * 16 + frow;
            int coll = nw * 32 + ni * 8 + 2 * fcol;
            float* a = acc[mi][ni];
            if (row < M)
                *reinterpret_cast<float2*>(C + (size_t)row * NT + bn + coll) =
                    make_float2(a[0], a[1]);
            if (row + 8 < M)
                *reinterpret_cast<float2*>(C + (size_t)(row + 8) * NT + bn + coll) =
                    make_float2(a[2], a[3]);
        }
    }

#pragma unroll
    for (int ni = 0; ni < 4; ni++) {
        float s0 = 0.f, s1 = 0.f, q0 = 0.f, q1 = 0.f;
#pragma unroll
        for (int mi = 0; mi < 4; mi++) {
            float* a = acc[mi][ni];
            s0 += a[0] + a[2];
            s1 += a[1] + a[3];
            q0 += a[0] * a[0] + a[2] * a[2];
            q1 += a[1] * a[1] + a[3] * a[3];
        }
#pragma unroll
        for (int off = 4; off < 32; off <<= 1) {
            s0 += __shfl_xor_sync(0xffffffff, s0, off);
            s1 += __shfl_xor_sync(0xffffffff, s1, off);
            q0 += __shfl_xor_sync(0xffffffff, q0, off);
            q1 += __shfl_xor_sync(0xffffffff, q1, off);
        }
        if (lane < 4) {
            int coll = nw * 32 + ni * 8 + 2 * fcol;
            atomicAdd(&ssum[coll], s0);
            atomicAdd(&ssum[coll + 1], s1);
            atomicAdd(&ssq[coll], q0);
            atomicAdd(&ssq[coll + 1], q1);
        }
    }
    __syncthreads();
    if (tid < 128) {
        atomicAdd(&stats_out[bn + tid], ssum[tid]);
        atomicAdd(&stats_out[NT + bn + tid], ssq[tid]);
    }
}

// ---------------- host orchestration ----------------

extern "C" void kernel_launch(void* const* d_in, const int* in_sizes, int n_in,
                              void* d_out, int out_size) {
    const float* feat       = (const float*)d_in[0];
    const int*   src        = (const int*)d_in[1];
    const int*   dst        = (const int*)d_in[2];
    const int*   graph_ids  = (const int*)d_in[3];
    const int*   mask_nodes = (const int*)d_in[4];
    const float* mask_token = (const float*)d_in[5];
    const float* enc_W1 = (const float*)d_in[6];
    const float* enc_g1 = (const float*)d_in[7];
    const float* enc_b1 = (const float*)d_in[8];
    const float* enc_W2 = (const float*)d_in[9];
    const float* enc_g2 = (const float*)d_in[10];
    const float* enc_b2 = (const float*)d_in[11];
    const float* con_W1 = (const float*)d_in[12];
    const float* con_g1 = (const float*)d_in[13];
    const float* con_b1 = (const float*)d_in[14];
    const float* con_W2 = (const float*)d_in[15];
    const float* con_g2 = (const float*)d_in[16];
    const float* con_b2 = (const float*)d_in[17];
    const float* pW1 = (const float*)d_in[18];
    const float* pb1 = (const float*)d_in[19];
    const float* pW2 = (const float*)d_in[20];
    const float* pb2 = (const float*)d_in[21];
    int nMask = in_sizes[4];

    float *x, *pool, *statsArena, *p2, *norms;
    float *h, *agg, *z1, *z2;
    float *w1h, *w1l, *w2h, *w2l;
    int *rowptr, *cnt, *colidx;
    cudaGetSymbolAddress((void**)&x, g_x);
    cudaGetSymbolAddress((void**)&h, g_h);
    cudaGetSymbolAddress((void**)&agg, g_agg);
    cudaGetSymbolAddress((void**)&z1, g_z1);
    cudaGetSymbolAddress((void**)&z2, g_z2);
    cudaGetSymbolAddress((void**)&statsArena, g_statsArena);
    cudaGetSymbolAddress((void**)&pool, g_pool);
    cudaGetSymbolAddress((void**)&p2, g_p2);
    cudaGetSymbolAddress((void**)&norms, g_norms);
    cudaGetSymbolAddress((void**)&w1h, g_W1T_hi);
    cudaGetSymbolAddress((void**)&w1l, g_W1T_lo);
    cudaGetSymbolAddress((void**)&w2h, g_W2T_hi);
    cudaGetSymbolAddress((void**)&w2l, g_W2T_lo);
    cudaGetSymbolAddress((void**)&rowptr, g_rowptr);
    cudaGetSymbolAddress((void**)&cnt, g_cnt);
    cudaGetSymbolAddress((void**)&colidx, g_col);

    cudaFuncSetAttribute(gemm_mma<0, HH, DD>, cudaFuncAttributeMaxDynamicSharedMemorySize, GEMM_SMEM);
    cudaFuncSetAttribute(gemm_mma<1, DD, HH>, cudaFuncAttributeMaxDynamicSharedMemorySize, GEMM_SMEM);

    // ---- prep ----
    cudaMemsetAsync(cnt, 0, NN * sizeof(int));
    count_kernel<<<(EE + 255) / 256, 256>>>(dst, cnt);
    scan_kernel<<<1, 1024>>>(cnt, rowptr);
    cudaMemsetAsync(cnt, 0, NN * sizeof(int));
    fill_kernel<<<(EE + 255) / 256, 256>>>(src, dst, rowptr, cnt, colidx);

    const int T1 = ENC_W;
    tsplit<<<(T1 + 255) / 256, 256>>>(enc_W1, w1h, w1l, DD, HH, T1);
    tsplit<<<(T1 + 255) / 256, 256>>>(con_W1, w1h + T1, w1l + T1, DD, HH, T1);
    tsplit<<<(T1 + 255) / 256, 256>>>(enc_W2, w2h, w2l, HH, DD, T1);
    tsplit<<<(T1 + 255) / 256, 256>>>(con_W2, w2h + T1, w2l + T1, HH, DD, T1);

    cudaMemcpyAsync(x, feat, (size_t)NN * DD * sizeof(float), cudaMemcpyDeviceToDevice);
    mask_kernel<<<(nMask * DD + 255) / 256, 256>>>(x, mask_nodes, mask_token, nMask);

    cudaMemsetAsync(pool, 0, 2 * BB * LL * DD * sizeof(float));
    cudaMemsetAsync(statsArena, 0, 2 * LL * 2 * 512 * sizeof(float));
    cudaMemsetAsync(d_out, 0, sizeof(float));

    // ---- both encoders, batched per stage (enc axis = blockIdx.y/z) ----
    const int GB = (NN + 127) / 128;   // 391
    for (int l = 0; l < LL; l++) {
        gather_kernel<<<dim3((NN * 32 + 255) / 256, 2), 256>>>(
            l == 0 ? x : h,
            l == 0 ? feat : h + (size_t)NN * DD,
            rowptr, colidx, agg);

        float* st1 = statsArena + l * 1024;        // enc stride applied in-kernel
        float* st2 = st1 + 512;
        gemm_mma<0, HH, DD><<<dim3(GB, HH / 128, 2), 256, GEMM_SMEM>>>(
            agg, w1h + (size_t)l * HH * DD, w1l + (size_t)l * HH * DD,
            z1, st1, nullptr, nullptr, nullptr, nullptr, nullptr, NN);
        gemm_mma<1, DD, HH><<<dim3(GB, 1, 2), 256, GEMM_SMEM>>>(
            z1, w2h + (size_t)l * DD * HH, w2l + (size_t)l * DD * HH,
            z2, st2, st1,
            enc_g1 + l * HH, con_g1 + l * HH, enc_b1 + l * HH, con_b1 + l * HH, NN);

        bnrelu_pool<<<dim3((NN * DD / 4 + 255) / 256, 2), 256>>>(
            z2, st2, enc_g2 + l * DD, con_g2 + l * DD,
            enc_b2 + l * DD, con_b2 + l * DD, graph_ids, h, pool, l * DD);
    }

    // ---- tail ----
    proj_kernel<<<dim3(BB, 2), 192>>>(pool, pW1, pb1, pW2, pb2, p2);
    norms_kernel<<<2 * BB, 128>>>(p2, norms);
    loss_kernel<<<BB, 256>>>(p2 + BB * 128, p2, norms + BB, norms, (float*)d_out);
}

// round 11
// speedup vs baseline: 3.1304x; 1.0787x over previous
#include <cuda_runtime.h>
#include <cuda_bf16.h>
#include <math.h>
#include <stdint.h>

#define NN 50000
#define EE 800000
#define BB 256
#define DD 128
#define HH 256
#define LL 3
#define TEMP 0.2f
#define BN_EPS 1e-5f

// ---------------- scratch (device globals) ----------------
// bf16 node features: [enc][node][feat]  (layer-0 inputs and per-layer h)
__device__ __align__(16) __nv_bfloat16 g_xb[2][(size_t)NN * DD];
__device__ __align__(16) __nv_bfloat16 g_hb[2][(size_t)NN * DD];
__device__ __align__(16) __nv_bfloat16 g_z1b[2][(size_t)NN * HH];
__device__ __align__(16) float g_agg[2][(size_t)NN * DD];
__device__ __align__(16) float g_z2[2][(size_t)NN * DD];
__device__ __align__(16) float g_statsArena[2 * LL * 2 * 512];
__device__ __align__(16) float g_pool[2 * BB * LL * DD];
__device__ __align__(16) float g_p2[2 * BB * 128];
__device__ float g_norms[2 * BB];
__device__ __align__(16) float g_W1T_hi[2 * LL * HH * DD];
__device__ __align__(16) float g_W1T_lo[2 * LL * HH * DD];
__device__ __align__(16) float g_W2T_hi[2 * LL * DD * HH];
__device__ __align__(16) float g_W2T_lo[2 * LL * DD * HH];
__device__ int g_rowptr[NN + 1];
__device__ int g_cnt[NN];
__device__ int g_col[EE];

#define ENC_W (LL * DD * HH)
#define ENC_ST (LL * 1024)

// ---------------- helpers ----------------
__device__ __forceinline__ float tf32_round(float x) {
    uint32_t u;
    asm("cvt.rna.tf32.f32 %0, %1;" : "=r"(u) : "f"(x));
    return __uint_as_float(u);
}
__device__ __forceinline__ void red_add_v4(float* p, float4 v) {
    asm volatile("red.global.add.v4.f32 [%0], {%1,%2,%3,%4};"
                 :: "l"(p), "f"(v.x), "f"(v.y), "f"(v.z), "f"(v.w) : "memory");
}
__device__ __forceinline__ void mma_tf32(float* c, const uint32_t* a, const uint32_t* b) {
    asm volatile(
        "mma.sync.aligned.m16n8k8.row.col.f32.tf32.tf32.f32 "
        "{%0,%1,%2,%3}, {%4,%5,%6,%7}, {%8,%9}, {%0,%1,%2,%3};"
        : "+f"(c[0]), "+f"(c[1]), "+f"(c[2]), "+f"(c[3])
        : "r"(a[0]), "r"(a[1]), "r"(a[2]), "r"(a[3]), "r"(b[0]), "r"(b[1]));
}
__device__ __forceinline__ float4 bf8_to_f4a(uint2 u, float4* hi4) {
    __nv_bfloat162 b0 = *reinterpret_cast<__nv_bfloat162*>(&u.x);
    __nv_bfloat162 b1 = *reinterpret_cast<__nv_bfloat162*>(&u.y);
    float2 f0 = __bfloat1622float2(b0);
    float2 f1 = __bfloat1622float2(b1);
    (void)hi4;
    return make_float4(f0.x, f0.y, f1.x, f1.y);
}
__device__ __forceinline__ uint2 f4_to_bf8(float4 v) {
    __nv_bfloat162 p0 = __floats2bfloat162_rn(v.x, v.y);
    __nv_bfloat162 p1 = __floats2bfloat162_rn(v.z, v.w);
    uint2 u;
    u.x = *reinterpret_cast<uint32_t*>(&p0);
    u.y = *reinterpret_cast<uint32_t*>(&p1);
    return u;
}

// ---------------- CSR build ----------------
__global__ void count_kernel(const int* __restrict__ dst, int* __restrict__ cnt) {
    int e = blockIdx.x * blockDim.x + threadIdx.x;
    if (e < EE) atomicAdd(&cnt[dst[e]], 1);
}

__global__ void scan_kernel(const int* __restrict__ cnt, int* __restrict__ rowptr) {
    __shared__ int wsums[32];
    __shared__ int s_carry;
    int t = threadIdx.x, lane = t & 31, w = t >> 5;
    if (t == 0) s_carry = 0;
    __syncthreads();
    for (int base = 0; base < NN; base += 1024) {
        int i = base + t;
        int v = (i < NN) ? cnt[i] : 0;
        int x = v;
#pragma unroll
        for (int o = 1; o < 32; o <<= 1) {
            int y = __shfl_up_sync(0xffffffff, x, o);
            if (lane >= o) x += y;
        }
        if (lane == 31) wsums[w] = x;
        __syncthreads();
        if (w == 0) {
            int s = wsums[lane];
#pragma unroll
            for (int o = 1; o < 32; o <<= 1) {
                int y = __shfl_up_sync(0xffffffff, s, o);
                if (lane >= o) s += y;
            }
            wsums[lane] = s;
        }
        __syncthreads();
        int excl = x - v + (w ? wsums[w - 1] : 0) + s_carry;
        if (i < NN) rowptr[i] = excl;
        __syncthreads();
        if (t == 1023) s_carry += x + wsums[30];
        __syncthreads();
    }
    if (t == 0) rowptr[NN] = s_carry;
}

__global__ void fill_kernel(const int* __restrict__ src, const int* __restrict__ dst,
                            const int* __restrict__ rowptr, int* __restrict__ cnt,
                            int* __restrict__ col) {
    int e = blockIdx.x * blockDim.x + threadIdx.x;
    if (e >= EE) return;
    int d = dst[e];
    int pos = __ldg(rowptr + d) + atomicAdd(&cnt[d], 1);
    col[pos] = src[e];
}

// ---------- gather (bf16 in, fp32 out): agg[n] = h[n] + sum_{m} h[m] ----------
__global__ void gather_kernel(const __nv_bfloat16* __restrict__ hin0,
                              const __nv_bfloat16* __restrict__ hin1,
                              const int* __restrict__ rowptr, const int* __restrict__ col,
                              float* __restrict__ agg) {
    int enc = blockIdx.y;
    const __nv_bfloat16* hin = enc ? hin1 : hin0;
    agg += (size_t)enc * NN * DD;
    int wid = (blockIdx.x * blockDim.x + threadIdx.x) >> 5;
    if (wid >= NN) return;
    int lane = threadIdx.x & 31;
    int r0 = __ldg(rowptr + wid), r1 = __ldg(rowptr + wid + 1);
    uint2 us = *reinterpret_cast<const uint2*>(hin + (size_t)wid * DD + lane * 4);
    float4 acc = bf8_to_f4a(us, nullptr);
    for (int base = r0; base < r1; base += 32) {
        int idx = (base + lane < r1) ? __ldg(col + base + lane) : 0;
        int m = min(32, r1 - base);
        int j = 0;
        for (; j + 4 <= m; j += 4) {
            int n0 = __shfl_sync(0xffffffff, idx, j);
            int n1 = __shfl_sync(0xffffffff, idx, j + 1);
            int n2 = __shfl_sync(0xffffffff, idx, j + 2);
            int n3 = __shfl_sync(0xffffffff, idx, j + 3);
            uint2 u0 = *reinterpret_cast<const uint2*>(hin + (size_t)n0 * DD + lane * 4);
            uint2 u1 = *reinterpret_cast<const uint2*>(hin + (size_t)n1 * DD + lane * 4);
            uint2 u2 = *reinterpret_cast<const uint2*>(hin + (size_t)n2 * DD + lane * 4);
            uint2 u3 = *reinterpret_cast<const uint2*>(hin + (size_t)n3 * DD + lane * 4);
            float4 v0 = bf8_to_f4a(u0, nullptr);
            float4 v1 = bf8_to_f4a(u1, nullptr);
            float4 v2 = bf8_to_f4a(u2, nullptr);
            float4 v3 = bf8_to_f4a(u3, nullptr);
            acc.x += v0.x + v1.x + v2.x + v3.x;
            acc.y += v0.y + v1.y + v2.y + v3.y;
            acc.z += v0.z + v1.z + v2.z + v3.z;
            acc.w += v0.w + v1.w + v2.w + v3.w;
        }
        for (; j < m; j++) {
            int n = __shfl_sync(0xffffffff, idx, j);
            uint2 u = *reinterpret_cast<const uint2*>(hin + (size_t)n * DD + lane * 4);
            float4 v = bf8_to_f4a(u, nullptr);
            acc.x += v.x; acc.y += v.y; acc.z += v.z; acc.w += v.w;
        }
    }
    *reinterpret_cast<float4*>(agg + (size_t)wid * DD + lane * 4) = acc;
}

// ---------------- small kernels ----------------
// feat -> bf16 into both encoder slots
__global__ void conv_kernel(const float* __restrict__ feat,
                            __nv_bfloat16* __restrict__ xb0,
                            __nv_bfloat16* __restrict__ xb1) {
    int idx = blockIdx.x * blockDim.x + threadIdx.x;
    if (idx >= NN * DD / 4) return;
    float4 v = reinterpret_cast<const float4*>(feat)[idx];
    uint2 u = f4_to_bf8(v);
    *reinterpret_cast<uint2*>(xb0 + (size_t)idx * 4) = u;
    *reinterpret_cast<uint2*>(xb1 + (size_t)idx * 4) = u;
}

__global__ void mask_kernel(__nv_bfloat16* __restrict__ x, const int* __restrict__ idx,
                            const float* __restrict__ tok, int nMask) {
    int i = blockIdx.x * blockDim.x + threadIdx.x;
    if (i >= nMask * DD) return;
    int m = i >> 7, c = i & 127;
    x[(size_t)idx[m] * DD + c] = __float2bfloat16_rn(tok[c]);
}

// h(bf16) = relu(bn(z2)); pool accumulates the fp32 value
__global__ void bnrelu_pool(const float* __restrict__ Z, const float* __restrict__ stats,
                            const float* __restrict__ g0, const float* __restrict__ g1,
                            const float* __restrict__ b0, const float* __restrict__ b1,
                            const int* __restrict__ gid, __nv_bfloat16* __restrict__ hb,
                            float* __restrict__ pool, int colOff) {
    int enc = blockIdx.y;
    Z += (size_t)enc * NN * DD;
    hb += (size_t)enc * NN * DD;
    stats += (size_t)enc * ENC_ST;
    pool += (size_t)enc * BB * LL * DD;
    const float* g = enc ? g1 : g0;
    const float* b = enc ? b1 : b0;

    __shared__ __align__(16) float sab[2 * DD];
    int t = threadIdx.x;
    if (t < DD) {
        float m = stats[t] * (1.0f / NN);
        float var = stats[DD + t] * (1.0f / NN) - m * m;
        float a = g[t] * rsqrtf(var + BN_EPS);
        sab[t] = a;
        sab[DD + t] = b[t] - m * a;
    }
    __syncthreads();
    int idx = blockIdx.x * blockDim.x + t;
    if (idx >= NN * DD / 4) return;
    int r = idx >> 5;
    int c = (idx & 31) * 4;
    float4 z = *reinterpret_cast<const float4*>(Z + (size_t)idx * 4);
    float4 sa = *reinterpret_cast<const float4*>(sab + c);
    float4 sc = *reinterpret_cast<const float4*>(sab + DD + c);
    float4 v;
    v.x = fmaxf(fmaf(z.x, sa.x, sc.x), 0.f);
    v.y = fmaxf(fmaf(z.y, sa.y, sc.y), 0.f);
    v.z = fmaxf(fmaf(z.z, sa.z, sc.z), 0.f);
    v.w = fmaxf(fmaf(z.w, sa.w, sc.w), 0.f);
    *reinterpret_cast<uint2*>(hb + (size_t)idx * 4) = f4_to_bf8(v);
    red_add_v4(&pool[(size_t)gid[r] * (LL * DD) + colOff + c], v);
}

__global__ void proj_kernel(const float* __restrict__ pool, const float* __restrict__ pW1,
                            const float* __restrict__ pb1, const float* __restrict__ pW2,
                            const float* __restrict__ pb2, float* __restrict__ out) {
    __shared__ float row[LL * DD];
    __shared__ float h1[192];
    int i = blockIdx.x + blockIdx.y * BB;
    int t = threadIdx.x;
    for (int k = t; k < LL * DD; k += 192) row[k] = pool[(size_t)i * (LL * DD) + k];
    __syncthreads();
    float s = pb1[t];
    for (int k = 0; k < LL * DD; k++) s += row[k] * pW1[(size_t)k * 192 + t];
    h1[t] = fmaxf(s, 0.f);
    __syncthreads();
    if (t < 128) {
        float s2 = pb2[t];
        for (int k = 0; k < 192; k++) s2 += h1[k] * pW2[(size_t)k * 128 + t];
        out[(size_t)i * 128 + t] = s2;
    }
}

__global__ void norms_kernel(const float* __restrict__ p, float* __restrict__ nrm) {
    int row = blockIdx.x, t = threadIdx.x;
    float v = p[(size_t)row * 128 + t];
    v *= v;
    for (int o = 16; o; o >>= 1) v += __shfl_down_sync(0xffffffff, v, o);
    __shared__ float ws[4];
    if ((t & 31) == 0) ws[t >> 5] = v;
    __syncthreads();
    if (t == 0) nrm[row] = sqrtf(ws[0] + ws[1] + ws[2] + ws[3]);
}

__global__ void loss_kernel(const float* __restrict__ ch, const float* __restrict__ cm,
                            const float* __restrict__ n_ch, const float* __restrict__ n_cm,
                            float* __restrict__ out) {
    int i = blockIdx.x;
    int t = threadIdx.x;
    __shared__ float sh[128];
    __shared__ float red[256];
    __shared__ float posv;
    if (t < 128) sh[t] = ch[(size_t)i * 128 + t];
    __syncthreads();
    float d = 0.f;
    const float* rowj = cm + (size_t)t * 128;
    for (int k = 0; k < 128; k++) d += sh[k] * rowj[k];
    float s = expf(d / (n_ch[i] * n_cm[t]) * (1.0f / TEMP));
    if (t == i) posv = s;
    red[t] = s;
    __syncthreads();
    for (int o = 128; o; o >>= 1) {
        if (t < o) red[t] += red[t + o];
        __syncthreads();
    }
    if (t == 0) {
        float sum = red[0];
        float li = -logf(posv / (sum - posv));
        atomicAdd(out, li * (1.0f / BB));
    }
}

// weight prep: all 4 weight tensors in one launch (blockIdx.y selects)
__global__ void tsplit4(const float* __restrict__ W1e, const float* __restrict__ W1c,
                        const float* __restrict__ W2e, const float* __restrict__ W2c,
                        float* __restrict__ w1h, float* __restrict__ w1l,
                        float* __restrict__ w2h, float* __restrict__ w2l) {
    int which = blockIdx.y;
    const float* W;
    float *hi, *lo;
    int K, N;
    if (which == 0)      { W = W1e; hi = w1h;         lo = w1l;         K = DD; N = HH; }
    else if (which == 1) { W = W1c; hi = w1h + ENC_W; lo = w1l + ENC_W; K = DD; N = HH; }
    else if (which == 2) { W = W2e; hi = w2h;         lo = w2l;         K = HH; N = DD; }
    else                 { W = W2c; hi = w2h + ENC_W; lo = w2l + ENC_W; K = HH; N = DD; }
    int i = blockIdx.x * blockDim.x + threadIdx.x;
    if (i >= ENC_W) return;
    int l = i / (K * N), rem = i % (K * N);
    int k = rem / N, n = rem % N;
    float v = W[i];
    float h = tf32_round(v);
    size_t o = (size_t)l * K * N + (size_t)n * K + k;
    hi[o] = h;
    lo[o] = v - h;
}

// ---------------- 2xTF32 mma.sync GEMM (both encoders via blockIdx.z) ---------
// MODE 0: A fp32 (agg), C bf16 (z1).  MODE 1: A bf16 (z1) with fused BN+ReLU, C fp32 (z2).
#define PAD 36
#define GEMM_SMEM ((3 * 128 * PAD + 2 * 256) * 4)   // 57344 B

template <int MODE, int NT, int KT>
__global__ __launch_bounds__(256, 2)
void gemm_mma(const void* __restrict__ Av, const float* __restrict__ Bh,
              const float* __restrict__ Bl, void* __restrict__ Cv,
              float* __restrict__ stats_out, const float* __restrict__ stats_in,
              const float* __restrict__ g0, const float* __restrict__ g1,
              const float* __restrict__ b0, const float* __restrict__ b1, int M) {
    const int enc = blockIdx.z;
    Bh += (size_t)enc * ENC_W;
    Bl += (size_t)enc * ENC_W;
    stats_out += (size_t)enc * ENC_ST;
    const float* g = enc ? g1 : g0;
    const float* b = enc ? b1 : b0;

    extern __shared__ float sm[];
    float* As  = sm;
    float* Bhs = As + 128 * PAD;
    float* Bls = Bhs + 128 * PAD;
    float* sab = Bls + 128 * PAD;
    __shared__ float ssum[128], ssq[128];

    const int tid = threadIdx.x;
    const int lane = tid & 31, w = tid >> 5;
    const int mw = w >> 2, nw = w & 3;
    const int bm = blockIdx.x * 128, bn = blockIdx.y * 128;

    if (MODE == 1) {
        const float* si = stats_in + (size_t)enc * ENC_ST;
        for (int i = tid; i < KT; i += 256) {
            float m = si[i] * (1.0f / NN);
            float var = si[KT + i] * (1.0f / NN) - m * m;
            float a = g[i] * rsqrtf(var + BN_EPS);
            sab[i] = a;
            sab[KT + i] = b[i] - m * a;
        }
        __syncthreads();
    }

    float acc[4][4][4];
#pragma unroll
    for (int mi = 0; mi < 4; mi++)
#pragma unroll
        for (int ni = 0; ni < 4; ni++)
#pragma unroll
            for (int r = 0; r < 4; r++) acc[mi][ni][r] = 0.f;

    const int lrow = tid >> 1;
    const int lcol0 = (tid & 1) * 16;
    const bool rok = (bm + lrow) < M;
    const float* ArowF = (MODE == 0)
        ? (const float*)Av + (size_t)enc * NN * KT + (size_t)(bm + lrow) * KT : nullptr;
    const __nv_bfloat16* ArowB = (MODE == 1)
        ? (const __nv_bfloat16*)Av + (size_t)enc * NN * KT + (size_t)(bm + lrow) * KT : nullptr;
    const float* Bhrow = Bh + (size_t)(bn + lrow) * KT;
    const float* Blrow = Bl + (size_t)(bn + lrow) * KT;

    const int frow = lane >> 2;
    const int fcol = lane & 3;

    for (int k0 = 0; k0 < KT; k0 += 32) {
        // ---- stage A ----
        if (MODE == 0) {
#pragma unroll
            for (int i = 0; i < 4; i++) {
                int col = lcol0 + i * 4;
                float4 v = make_float4(0.f, 0.f, 0.f, 0.f);
                if (rok) v = *reinterpret_cast<const float4*>(ArowF + k0 + col);
                As[lrow * PAD + col + 0] = tf32_round(v.x);
                As[lrow * PAD + col + 1] = tf32_round(v.y);
                As[lrow * PAD + col + 2] = tf32_round(v.z);
                As[lrow * PAD + col + 3] = tf32_round(v.w);
            }
        } else {
#pragma unroll
            for (int half = 0; half < 2; half++) {
                uint4 u = make_uint4(0, 0, 0, 0);
                if (rok) u = *reinterpret_cast<const uint4*>(ArowB + k0 + lcol0 + half * 8);
                uint32_t uu[4] = {u.x, u.y, u.z, u.w};
#pragma unroll
                for (int j = 0; j < 4; j++) {
                    __nv_bfloat162 bb = *reinterpret_cast<__nv_bfloat162*>(&uu[j]);
                    float2 f = __bfloat1622float2(bb);
                    int col = lcol0 + half * 8 + j * 2;
                    float a0 = fmaxf(fmaf(f.x, sab[col], sab[KT + col]), 0.f);
                    float a1 = fmaxf(fmaf(f.y, sab[col + 1], sab[KT + col + 1]), 0.f);
                    As[lrow * PAD + col] = tf32_round(a0);
                    As[lrow * PAD + col + 1] = tf32_round(a1);
                }
            }
        }
        // ---- stage B ----
#pragma unroll
        for (int i = 0; i < 4; i++) {
            int col = lcol0 + i * 4;
            float4 vh = *reinterpret_cast<const float4*>(Bhrow + k0 + col);
            float4 vl = *reinterpret_cast<const float4*>(Blrow + k0 + col);
            *reinterpret_cast<float4*>(Bhs + lrow * PAD + col) = vh;
            *reinterpret_cast<float4*>(Bls + lrow * PAD + col) = vl;
        }
        __syncthreads();

#pragma unroll
        for (int kk = 0; kk < 4; kk++) {
            const int k = kk * 8;
            uint32_t af[4][4];
#pragma unroll
            for (int mi = 0; mi < 4; mi++) {
                int r0 = mw * 64 + mi * 16 + frow;
                int c0 = k + fcol;
                af[mi][0] = __float_as_uint(As[r0 * PAD + c0]);
                af[mi][1] = __float_as_uint(As[(r0 + 8) * PAD + c0]);
                af[mi][2] = __float_as_uint(As[r0 * PAD + c0 + 4]);
                af[mi][3] = __float_as_uint(As[(r0 + 8) * PAD + c0 + 4]);
            }
            uint32_t bfh[4][2], bfl[4][2];
#pragma unroll
            for (int ni = 0; ni < 4; ni++) {
                int n0 = nw * 32 + ni * 8 + frow;
                int kb = k + fcol;
                bfh[ni][0] = __float_as_uint(Bhs[n0 * PAD + kb]);
                bfh[ni][1] = __float_as_uint(Bhs[n0 * PAD + kb + 4]);
                bfl[ni][0] = __float_as_uint(Bls[n0 * PAD + kb]);
                bfl[ni][1] = __float_as_uint(Bls[n0 * PAD + kb + 4]);
            }
#pragma unroll
            for (int mi = 0; mi < 4; mi++)
#pragma unroll
                for (int ni = 0; ni < 4; ni++) {
                    mma_tf32(acc[mi][ni], af[mi], bfh[ni]);
                    mma_tf32(acc[mi][ni], af[mi], bfl[ni]);
                }
        }
        __syncthreads();
    }

    // ---- epilogue: C store + fused column stats ----
    if (tid < 128) { ssum[tid] = 0.f; ssq[tid] = 0.f; }
    __syncthreads();

#pragma unroll
    for (int mi = 0; mi < 4; mi++) {
#pragma unroll
        for (int ni = 0; ni < 4; ni++) {
            int row = bm + mw * 64 + mi * 16 + frow;
            int coll = nw * 32 + ni * 8 + 2 * fcol;
            float* a = acc[mi][ni];
            if (MODE == 0) {
                __nv_bfloat16* Cb = (__nv_bfloat16*)Cv + (size_t)enc * NN * NT;
                if (row < M)
                    *reinterpret_cast<__nv_bfloat162*>(Cb + (size_t)row * NT + bn + coll) =
                        __floats2bfloat162_rn(a[0], a[1]);
                if (row + 8 < M)
                    *reinterpret_cast<__nv_bfloat162*>(Cb + (size_t)(row + 8) * NT + bn + coll) =
                        __floats2bfloat162_rn(a[2], a[3]);
            } else {
                float* Cf = (float*)Cv + (size_t)enc * NN * NT;
                if (row < M)
                    *reinterpret_cast<float2*>(Cf + (size_t)row * NT + bn + coll) =
                        make_float2(a[0], a[1]);
                if (row + 8 < M)
                    *reinterpret_cast<float2*>(Cf + (size_t)(row + 8) * NT + bn + coll) =
                        make_float2(a[2], a[3]);
            }
        }
    }

#pragma unroll
    for (int ni = 0; ni < 4; ni++) {
        float s0 = 0.f, s1 = 0.f, q0 = 0.f, q1 = 0.f;
#pragma unroll
        for (int mi = 0; mi < 4; mi++) {
            float* a = acc[mi][ni];
            s0 += a[0] + a[2];
            s1 += a[1] + a[3];
            q0 += a[0] * a[0] + a[2] * a[2];
            q1 += a[1] * a[1] + a[3] * a[3];
        }
#pragma unroll
        for (int off = 4; off < 32; off <<= 1) {
            s0 += __shfl_xor_sync(0xffffffff, s0, off);
            s1 += __shfl_xor_sync(0xffffffff, s1, off);
            q0 += __shfl_xor_sync(0xffffffff, q0, off);
            q1 += __shfl_xor_sync(0xffffffff, q1, off);
        }
        if (lane < 4) {
            int coll = nw * 32 + ni * 8 + 2 * fcol;
            atomicAdd(&ssum[coll], s0);
            atomicAdd(&ssum[coll + 1], s1);
            atomicAdd(&ssq[coll], q0);
            atomicAdd(&ssq[coll + 1], q1);
        }
    }
    __syncthreads();
    if (tid < 128) {
        atomicAdd(&stats_out[bn + tid], ssum[tid]);
        atomicAdd(&stats_out[NT + bn + tid], ssq[tid]);
    }
}

// ---------------- host orchestration ----------------

extern "C" void kernel_launch(void* const* d_in, const int* in_sizes, int n_in,
                              void* d_out, int out_size) {
    const float* feat       = (const float*)d_in[0];
    const int*   src        = (const int*)d_in[1];
    const int*   dst        = (const int*)d_in[2];
    const int*   graph_ids  = (const int*)d_in[3];
    const int*   mask_nodes = (const int*)d_in[4];
    const float* mask_token = (const float*)d_in[5];
    const float* enc_W1 = (const float*)d_in[6];
    const float* enc_g1 = (const float*)d_in[7];
    const float* enc_b1 = (const float*)d_in[8];
    const float* enc_W2 = (const float*)d_in[9];
    const float* enc_g2 = (const float*)d_in[10];
    const float* enc_b2 = (const float*)d_in[11];
    const float* con_W1 = (const float*)d_in[12];
    const float* con_g1 = (const float*)d_in[13];
    const float* con_b1 = (const float*)d_in[14];
    const float* con_W2 = (const float*)d_in[15];
    const float* con_g2 = (const float*)d_in[16];
    const float* con_b2 = (const float*)d_in[17];
    const float* pW1 = (const float*)d_in[18];
    const float* pb1 = (const float*)d_in[19];
    const float* pW2 = (const float*)d_in[20];
    const float* pb2 = (const float*)d_in[21];
    int nMask = in_sizes[4];

    float *pool, *statsArena, *p2, *norms, *agg, *z2;
    __nv_bfloat16 *xb, *hb, *z1b;
    float *w1h, *w1l, *w2h, *w2l;
    int *rowptr, *cnt, *colidx;
    cudaGetSymbolAddress((void**)&xb, g_xb);
    cudaGetSymbolAddress((void**)&hb, g_hb);
    cudaGetSymbolAddress((void**)&z1b, g_z1b);
    cudaGetSymbolAddress((void**)&agg, g_agg);
    cudaGetSymbolAddress((void**)&z2, g_z2);
    cudaGetSymbolAddress((void**)&statsArena, g_statsArena);
    cudaGetSymbolAddress((void**)&pool, g_pool);
    cudaGetSymbolAddress((void**)&p2, g_p2);
    cudaGetSymbolAddress((void**)&norms, g_norms);
    cudaGetSymbolAddress((void**)&w1h, g_W1T_hi);
    cudaGetSymbolAddress((void**)&w1l, g_W1T_lo);
    cudaGetSymbolAddress((void**)&w2h, g_W2T_hi);
    cudaGetSymbolAddress((void**)&w2l, g_W2T_lo);
    cudaGetSymbolAddress((void**)&rowptr, g_rowptr);
    cudaGetSymbolAddress((void**)&cnt, g_cnt);
    cudaGetSymbolAddress((void**)&colidx, g_col);

    cudaFuncSetAttribute(gemm_mma<0, HH, DD>, cudaFuncAttributeMaxDynamicSharedMemorySize, GEMM_SMEM);
    cudaFuncSetAttribute(gemm_mma<1, DD, HH>, cudaFuncAttributeMaxDynamicSharedMemorySize, GEMM_SMEM);

    // ---- prep ----
    cudaMemsetAsync(cnt, 0, NN * sizeof(int));
    count_kernel<<<(EE + 255) / 256, 256>>>(dst, cnt);
    scan_kernel<<<1, 1024>>>(cnt, rowptr);
    cudaMemsetAsync(cnt, 0, NN * sizeof(int));
    fill_kernel<<<(EE + 255) / 256, 256>>>(src, dst, rowptr, cnt, colidx);

    tsplit4<<<dim3((ENC_W + 255) / 256, 4), 256>>>(enc_W1, con_W1, enc_W2, con_W2,
                                                   w1h, w1l, w2h, w2l);

    conv_kernel<<<(NN * DD / 4 + 255) / 256, 256>>>(feat, xb, xb + (size_t)NN * DD);
    mask_kernel<<<(nMask * DD + 255) / 256, 256>>>(xb, mask_nodes, mask_token, nMask);

    cudaMemsetAsync(pool, 0, 2 * BB * LL * DD * sizeof(float));
    cudaMemsetAsync(statsArena, 0, 2 * LL * 2 * 512 * sizeof(float));
    cudaMemsetAsync(d_out, 0, sizeof(float));

    // ---- both encoders, batched per stage ----
    const int GB = (NN + 127) / 128;   // 391
    for (int l = 0; l < LL; l++) {
        const __nv_bfloat16* in0 = l == 0 ? xb : hb;
        const __nv_bfloat16* in1 = (l == 0 ? xb : hb) + (size_t)NN * DD;
        gather_kernel<<<dim3((NN * 32 + 255) / 256, 2), 256>>>(in0, in1, rowptr, colidx, agg);

        float* st1 = statsArena + l * 1024;
        float* st2 = st1 + 512;
        gemm_mma<0, HH, DD><<<dim3(GB, HH / 128, 2), 256, GEMM_SMEM>>>(
            agg, w1h + (size_t)l * HH * DD, w1l + (size_t)l * HH * DD,
            z1b, st1, nullptr, nullptr, nullptr, nullptr, nullptr, NN);
        gemm_mma<1, DD, HH><<<dim3(GB, 1, 2), 256, GEMM_SMEM>>>(
            z1b, w2h + (size_t)l * DD * HH, w2l + (size_t)l * DD * HH,
            z2, st2, st1,
            enc_g1 + l * HH, con_g1 + l * HH, enc_b1 + l * HH, con_b1 + l * HH, NN);

        bnrelu_pool<<<dim3((NN * DD / 4 + 255) / 256, 2), 256>>>(
            z2, st2, enc_g2 + l * DD, con_g2 + l * DD,
            enc_b2 + l * DD, con_b2 + l * DD, graph_ids, hb, pool, l * DD);
    }

    // ---- tail ----
    proj_kernel<<<dim3(BB, 2), 192>>>(pool, pW1, pb1, pW2, pb2, p2);
    norms_kernel<<<2 * BB, 128>>>(p2, norms);
    loss_kernel<<<BB, 256>>>(p2 + BB * 128, p2, norms + BB, norms, (float*)d_out);
}